// round 1
// baseline (speedup 1.0000x reference)
#include <cuda_runtime.h>
#include <math.h>

#define T_SEQ 4096
#define C_DIM 768
#define N_HEAD 12
#define HEAD_D 64

// Scratch (device globals — no allocation allowed in kernel_launch)
__device__ float g_Q[N_HEAD * T_SEQ * HEAD_D];
__device__ float g_K[N_HEAD * T_SEQ * HEAD_D];
__device__ float g_V[N_HEAD * T_SEQ * HEAD_D];
__device__ float g_O[T_SEQ * C_DIM];

// ----------------------------------------------------------------------------
// Projection GEMM: y = x @ W^T   (W stored row-major (out,in) => dot over k)
// Tile: 64x64 output per block, BK=16, 16x16 threads, 4x4 per thread.
// blockIdx.z selects {wq, wk, wv}; output written head-split [H][T][D].
// ----------------------------------------------------------------------------
__global__ __launch_bounds__(256) void proj_kernel(
    const float* __restrict__ x,
    const float* __restrict__ wq,
    const float* __restrict__ wk,
    const float* __restrict__ wv)
{
    const float* W = (blockIdx.z == 0) ? wq : (blockIdx.z == 1) ? wk : wv;
    float* dst     = (blockIdx.z == 0) ? g_Q : (blockIdx.z == 1) ? g_K : g_V;

    __shared__ float As[64][17];
    __shared__ float Bs[64][17];

    int m0 = blockIdx.y * 64;
    int n0 = blockIdx.x * 64;
    int tx = threadIdx.x, ty = threadIdx.y;
    int tid = ty * 16 + tx;

    float acc[4][4];
#pragma unroll
    for (int i = 0; i < 4; i++)
#pragma unroll
        for (int j = 0; j < 4; j++) acc[i][j] = 0.0f;

    for (int k0 = 0; k0 < C_DIM; k0 += 16) {
#pragma unroll
        for (int i = 0; i < 4; i++) {
            int idx = tid + i * 256;           // 64*16 = 1024 elements
            int r = idx >> 4, c = idx & 15;
            As[r][c] = x[(m0 + r) * C_DIM + k0 + c];
            Bs[r][c] = W[(n0 + r) * C_DIM + k0 + c];
        }
        __syncthreads();
#pragma unroll
        for (int kk = 0; kk < 16; kk++) {
            float a[4], b[4];
#pragma unroll
            for (int i = 0; i < 4; i++) a[i] = As[ty * 4 + i][kk];
#pragma unroll
            for (int j = 0; j < 4; j++) b[j] = Bs[tx * 4 + j][kk];
#pragma unroll
            for (int i = 0; i < 4; i++)
#pragma unroll
                for (int j = 0; j < 4; j++) acc[i][j] += a[i] * b[j];
        }
        __syncthreads();
    }

    int head = blockIdx.x;  // BN == HEAD_D == 64
#pragma unroll
    for (int i = 0; i < 4; i++) {
        int t = m0 + ty * 4 + i;
#pragma unroll
        for (int j = 0; j < 4; j++) {
            int d = tx * 4 + j;
            dst[(head * T_SEQ + t) * HEAD_D + d] = acc[i][j];
        }
    }
}

// ----------------------------------------------------------------------------
// Flash attention (causal). One block per (head, 64-row q tile).
// 16x16 threads; each thread owns a 4x4 patch of S and of O.
// Dynamic smem: Qs, Ks, Vs, Ss each 64 x 65 floats (pad to kill conflicts).
// ----------------------------------------------------------------------------
__global__ __launch_bounds__(256, 2) void attn_kernel()
{
    extern __shared__ float sm[];
    float* Qs = sm;
    float* Ks = sm + 64 * 65;
    float* Vs = sm + 2 * 64 * 65;
    float* Ss = sm + 3 * 64 * 65;

    int h  = blockIdx.y;
    int qi = gridDim.x - 1 - blockIdx.x;   // launch big tiles first
    int q0 = qi * 64;
    int tx = threadIdx.x, ty = threadIdx.y;
    int tid = ty * 16 + tx;

    const float* Qh = g_Q + h * T_SEQ * HEAD_D;
    const float* Kh = g_K + h * T_SEQ * HEAD_D;
    const float* Vh = g_V + h * T_SEQ * HEAD_D;

    // Load Q tile (64 x 64)
#pragma unroll
    for (int i = 0; i < 16; i++) {
        int idx = tid + i * 256;
        int r = idx >> 6, c = idx & 63;
        Qs[r * 65 + c] = Qh[(q0 + r) * HEAD_D + c];
    }

    float m_i[4], l_i[4], o[4][4];
#pragma unroll
    for (int i = 0; i < 4; i++) {
        m_i[i] = -1e30f;
        l_i[i] = 0.0f;
#pragma unroll
        for (int j = 0; j < 4; j++) o[i][j] = 0.0f;
    }

    const float scale = 0.125f;  // 1/sqrt(64)

    for (int j = 0; j <= qi; j++) {
        __syncthreads();   // prev iteration's smem reads done
        int k0 = j * 64;
#pragma unroll
        for (int i = 0; i < 16; i++) {
            int idx = tid + i * 256;
            int r = idx >> 6, c = idx & 63;
            Ks[r * 65 + c] = Kh[(k0 + r) * HEAD_D + c];
            Vs[r * 65 + c] = Vh[(k0 + r) * HEAD_D + c];
        }
        __syncthreads();

        // S = Q K^T (4x4 patch per thread)
        float s[4][4];
#pragma unroll
        for (int i = 0; i < 4; i++)
#pragma unroll
            for (int jj = 0; jj < 4; jj++) s[i][jj] = 0.0f;

#pragma unroll
        for (int kk = 0; kk < 64; kk++) {
            float a[4], b[4];
#pragma unroll
            for (int i = 0; i < 4; i++)  a[i]  = Qs[(ty * 4 + i) * 65 + kk];
#pragma unroll
            for (int jj = 0; jj < 4; jj++) b[jj] = Ks[(tx * 4 + jj) * 65 + kk];
#pragma unroll
            for (int i = 0; i < 4; i++)
#pragma unroll
                for (int jj = 0; jj < 4; jj++) s[i][jj] += a[i] * b[jj];
        }

        // scale + causal mask (only diagonal tile needs masking)
#pragma unroll
        for (int i = 0; i < 4; i++) {
#pragma unroll
            for (int jj = 0; jj < 4; jj++) {
                float v = s[i][jj] * scale;
                if (j == qi && (k0 + tx * 4 + jj) > (q0 + ty * 4 + i)) v = -1e30f;
                s[i][jj] = v;
            }
        }

        // online softmax per row (reduce across 16 tx lanes within a warp half)
#pragma unroll
        for (int i = 0; i < 4; i++) {
            float rmax = fmaxf(fmaxf(s[i][0], s[i][1]), fmaxf(s[i][2], s[i][3]));
#pragma unroll
            for (int off = 8; off >= 1; off >>= 1)
                rmax = fmaxf(rmax, __shfl_xor_sync(0xffffffffu, rmax, off));
            float mnew = fmaxf(m_i[i], rmax);
            float corr = __expf(m_i[i] - mnew);
            float rsum = 0.0f;
#pragma unroll
            for (int jj = 0; jj < 4; jj++) {
                s[i][jj] = __expf(s[i][jj] - mnew);
                rsum += s[i][jj];
            }
#pragma unroll
            for (int off = 8; off >= 1; off >>= 1)
                rsum += __shfl_xor_sync(0xffffffffu, rsum, off);
            l_i[i] = l_i[i] * corr + rsum;
            m_i[i] = mnew;
#pragma unroll
            for (int jj = 0; jj < 4; jj++) o[i][jj] *= corr;
        }

        // stage P in smem for the AV gemm
#pragma unroll
        for (int i = 0; i < 4; i++)
#pragma unroll
            for (int jj = 0; jj < 4; jj++)
                Ss[(ty * 4 + i) * 65 + tx * 4 + jj] = s[i][jj];
        __syncthreads();

        // O += P @ V
#pragma unroll
        for (int cc = 0; cc < 64; cc++) {
            float a[4], b[4];
#pragma unroll
            for (int i = 0; i < 4; i++)  a[i]  = Ss[(ty * 4 + i) * 65 + cc];
#pragma unroll
            for (int jj = 0; jj < 4; jj++) b[jj] = Vs[cc * 65 + tx * 4 + jj];
#pragma unroll
            for (int i = 0; i < 4; i++)
#pragma unroll
                for (int jj = 0; jj < 4; jj++) o[i][jj] += a[i] * b[jj];
        }
    }

    // normalize + write O in (T, C) layout for the output projection
#pragma unroll
    for (int i = 0; i < 4; i++) {
        float inv = 1.0f / l_i[i];
        int t = q0 + ty * 4 + i;
#pragma unroll
        for (int jj = 0; jj < 4; jj++)
            g_O[t * C_DIM + h * HEAD_D + tx * 4 + jj] = o[i][jj] * inv;
    }
}

// ----------------------------------------------------------------------------
// Output projection: out = O @ wo^T
// ----------------------------------------------------------------------------
__global__ __launch_bounds__(256) void out_kernel(
    const float* __restrict__ wo, float* __restrict__ out)
{
    __shared__ float As[64][17];
    __shared__ float Bs[64][17];

    int m0 = blockIdx.y * 64;
    int n0 = blockIdx.x * 64;
    int tx = threadIdx.x, ty = threadIdx.y;
    int tid = ty * 16 + tx;

    float acc[4][4];
#pragma unroll
    for (int i = 0; i < 4; i++)
#pragma unroll
        for (int j = 0; j < 4; j++) acc[i][j] = 0.0f;

    for (int k0 = 0; k0 < C_DIM; k0 += 16) {
#pragma unroll
        for (int i = 0; i < 4; i++) {
            int idx = tid + i * 256;
            int r = idx >> 4, c = idx & 15;
            As[r][c] = g_O[(m0 + r) * C_DIM + k0 + c];
            Bs[r][c] = wo[(n0 + r) * C_DIM + k0 + c];
        }
        __syncthreads();
#pragma unroll
        for (int kk = 0; kk < 16; kk++) {
            float a[4], b[4];
#pragma unroll
            for (int i = 0; i < 4; i++) a[i] = As[ty * 4 + i][kk];
#pragma unroll
            for (int j = 0; j < 4; j++) b[j] = Bs[tx * 4 + j][kk];
#pragma unroll
            for (int i = 0; i < 4; i++)
#pragma unroll
                for (int j = 0; j < 4; j++) acc[i][j] += a[i] * b[j];
        }
        __syncthreads();
    }

#pragma unroll
    for (int i = 0; i < 4; i++) {
        int t = m0 + ty * 4 + i;
#pragma unroll
        for (int j = 0; j < 4; j++)
            out[t * C_DIM + n0 + tx * 4 + j] = acc[i][j];
    }
}

// ----------------------------------------------------------------------------
extern "C" void kernel_launch(void* const* d_in, const int* in_sizes, int n_in,
                              void* d_out, int out_size)
{
    const float* x  = (const float*)d_in[0];
    const float* wq = (const float*)d_in[1];
    const float* wk = (const float*)d_in[2];
    const float* wv = (const float*)d_in[3];
    const float* wo = (const float*)d_in[4];
    float* out = (float*)d_out;

    dim3 blk(16, 16);

    // 1) QKV projections
    proj_kernel<<<dim3(C_DIM / 64, T_SEQ / 64, 3), blk>>>(x, wq, wk, wv);

    // 2) flash attention
    size_t smem = 4u * 64u * 65u * sizeof(float);  // 66560 B
    cudaFuncSetAttribute(attn_kernel,
                         cudaFuncAttributeMaxDynamicSharedMemorySize, (int)smem);
    attn_kernel<<<dim3(T_SEQ / 64, N_HEAD), blk, smem>>>();

    // 3) output projection
    out_kernel<<<dim3(C_DIM / 64, T_SEQ / 64), blk>>>(wo, out);
}

// round 4
// speedup vs baseline: 1.6100x; 1.6100x over previous
#include <cuda_runtime.h>
#include <cuda_bf16.h>
#include <cstdint>
#include <math.h>

#define T_SEQ 4096
#define C_DIM 768
#define N_HEAD 12
#define HEAD_D 64

// ----------------------------------------------------------------------------
// Scratch (device globals — no allocation allowed)
// ----------------------------------------------------------------------------
__device__ float g_Q[N_HEAD * T_SEQ * HEAD_D];
__device__ float g_K[N_HEAD * T_SEQ * HEAD_D];
__device__ float g_V[N_HEAD * T_SEQ * HEAD_D];
__device__ float g_O[T_SEQ * C_DIM];

// ----------------------------------------------------------------------------
// mma.sync helpers (baseline PTX ISA — compiles for plain sm_103)
// m16n8k16 row.col f32.bf16.bf16.f32
// A frag (4 regs): a0=A[g][2t,2t+1] a1=A[g+8][..] a2=A[g][2t+8,+9] a3=A[g+8][..]
// B frag (2 regs): b0=B[2t,2t+1][g] b1=B[2t+8,+9][g]   (B is k-major x n)
// C frag (4 f32):  c0=C[g][2t] c1=C[g][2t+1] c2=C[g+8][2t] c3=C[g+8][2t+1]
// where g = lane>>2, t = lane&3
// ----------------------------------------------------------------------------
__device__ __forceinline__ void mma_bf16(float* c, const uint32_t* a, const uint32_t* b) {
    asm volatile(
        "mma.sync.aligned.m16n8k16.row.col.f32.bf16.bf16.f32 "
        "{%0,%1,%2,%3}, {%4,%5,%6,%7}, {%8,%9}, {%0,%1,%2,%3};"
        : "+f"(c[0]), "+f"(c[1]), "+f"(c[2]), "+f"(c[3])
        : "r"(a[0]), "r"(a[1]), "r"(a[2]), "r"(a[3]), "r"(b[0]), "r"(b[1]));
}

__device__ __forceinline__ uint32_t pack_bf16(float x, float y) {
    __nv_bfloat162 h = __float22bfloat162_rn(make_float2(x, y));
    return *reinterpret_cast<uint32_t*>(&h);
}

// split two floats into packed hi (bf16x2) and lo (residual bf16x2)
__device__ __forceinline__ void split2(float x, float y, uint32_t& hi, uint32_t& lo) {
    __nv_bfloat162 h2 = __float22bfloat162_rn(make_float2(x, y));
    float rx = x - __bfloat162float(h2.x);
    float ry = y - __bfloat162float(h2.y);
    __nv_bfloat162 l2 = __float22bfloat162_rn(make_float2(rx, ry));
    hi = *reinterpret_cast<uint32_t*>(&h2);
    lo = *reinterpret_cast<uint32_t*>(&l2);
}

// 8 consecutive floats -> uint4 hi + uint4 lo (bf16x2 packed)
__device__ __forceinline__ void split8(const float* v, uint4& hi, uint4& lo) {
    uint32_t h[4], l[4];
#pragma unroll
    for (int i = 0; i < 4; i++) split2(v[2 * i], v[2 * i + 1], h[i], l[i]);
    hi = make_uint4(h[0], h[1], h[2], h[3]);
    lo = make_uint4(l[0], l[1], l[2], l[3]);
}

// ----------------------------------------------------------------------------
// Warp-MMA GEMM: C[M,N] = A[M,K] @ W[N,K]^T, fp32 in/out, bf16 hi/lo (3 MMAs).
// CTA tile: 128 x 64, K-chunk 64. 8 warps, each owns 16 rows x 64 cols.
// MODE 0: A = x, W in {wq,wk,wv} via blockIdx.z, dst = head-split g_Q/g_K/g_V.
// MODE 1: A = g_O, W = w0, dst = outp row-major.
// ----------------------------------------------------------------------------
#define SROW 72   // smem row stride in bf16 (144 B -> conflict-free frag loads)
static constexpr int GEMM_SMEM = (128 + 128 + 64 + 64) * SROW * 2;  // 55296 B

template <int MODE>
__global__ __launch_bounds__(256) void gemm_tc(
    const float* __restrict__ Ain,
    const float* __restrict__ w0, const float* __restrict__ w1,
    const float* __restrict__ w2, float* __restrict__ outp)
{
    extern __shared__ __nv_bfloat16 sb[];
    __nv_bfloat16* Ah = sb;
    __nv_bfloat16* Al = sb + 128 * SROW;
    __nv_bfloat16* Bh = sb + 256 * SROW;
    __nv_bfloat16* Bl = sb + 320 * SROW;

    const float* A;
    const float* W;
    if (MODE == 0) {
        A = Ain;
        W = (blockIdx.z == 0) ? w0 : (blockIdx.z == 1) ? w1 : w2;
    } else {
        A = g_O;
        W = w0;
    }

    const int tid = threadIdx.x;
    const int w = tid >> 5, lane = tid & 31;
    const int g = lane >> 2, t = lane & 3;
    const int m0 = blockIdx.y * 128;
    const int n0 = blockIdx.x * 64;

    float c[8][4];
#pragma unroll
    for (int i = 0; i < 8; i++)
#pragma unroll
        for (int j = 0; j < 4; j++) c[i][j] = 0.0f;

    for (int ch = 0; ch < C_DIM / 64; ch++) {
        const int k0 = ch * 64;
        // load + convert A tile (128 x 64)
#pragma unroll
        for (int p = 0; p < 4; p++) {
            int r = p * 32 + (tid >> 3);
            int c0 = (tid & 7) * 8;
            float vv[8];
            const float4* s4 = (const float4*)&A[(size_t)(m0 + r) * C_DIM + k0 + c0];
            *(float4*)&vv[0] = s4[0];
            *(float4*)&vv[4] = s4[1];
            uint4 hi, lo;
            split8(vv, hi, lo);
            *(uint4*)&Ah[r * SROW + c0] = hi;
            *(uint4*)&Al[r * SROW + c0] = lo;
        }
        // load + convert B tile (64 x 64)
#pragma unroll
        for (int p = 0; p < 2; p++) {
            int r = p * 32 + (tid >> 3);
            int c0 = (tid & 7) * 8;
            float vv[8];
            const float4* s4 = (const float4*)&W[(size_t)(n0 + r) * C_DIM + k0 + c0];
            *(float4*)&vv[0] = s4[0];
            *(float4*)&vv[4] = s4[1];
            uint4 hi, lo;
            split8(vv, hi, lo);
            *(uint4*)&Bh[r * SROW + c0] = hi;
            *(uint4*)&Bl[r * SROW + c0] = lo;
        }
        __syncthreads();

#pragma unroll
        for (int ks = 0; ks < 4; ks++) {
            uint32_t ah[4], al[4];
            int ab = (16 * w + g) * SROW + 16 * ks + 2 * t;
            ah[0] = *(uint32_t*)&Ah[ab];
            ah[1] = *(uint32_t*)&Ah[ab + 8 * SROW];
            ah[2] = *(uint32_t*)&Ah[ab + 8];
            ah[3] = *(uint32_t*)&Ah[ab + 8 * SROW + 8];
            al[0] = *(uint32_t*)&Al[ab];
            al[1] = *(uint32_t*)&Al[ab + 8 * SROW];
            al[2] = *(uint32_t*)&Al[ab + 8];
            al[3] = *(uint32_t*)&Al[ab + 8 * SROW + 8];
#pragma unroll
            for (int nt = 0; nt < 8; nt++) {
                int bb = (8 * nt + g) * SROW + 16 * ks + 2 * t;
                uint32_t bh[2], bl[2];
                bh[0] = *(uint32_t*)&Bh[bb];
                bh[1] = *(uint32_t*)&Bh[bb + 8];
                bl[0] = *(uint32_t*)&Bl[bb];
                bl[1] = *(uint32_t*)&Bl[bb + 8];
                mma_bf16(c[nt], ah, bh);
                mma_bf16(c[nt], ah, bl);
                mma_bf16(c[nt], al, bh);
            }
        }
        __syncthreads();
    }

    // epilogue
    const int r0 = m0 + 16 * w + g;
#pragma unroll
    for (int nt = 0; nt < 8; nt++) {
        int cb = 8 * nt + 2 * t;
        if (MODE == 0) {
            float* dst = (blockIdx.z == 0) ? g_Q : (blockIdx.z == 1) ? g_K : g_V;
            int head = blockIdx.x;  // N block == head dim
            *(float2*)&dst[((size_t)head * T_SEQ + r0) * HEAD_D + cb] =
                make_float2(c[nt][0], c[nt][1]);
            *(float2*)&dst[((size_t)head * T_SEQ + r0 + 8) * HEAD_D + cb] =
                make_float2(c[nt][2], c[nt][3]);
        } else {
            *(float2*)&outp[(size_t)r0 * C_DIM + n0 + cb] = make_float2(c[nt][0], c[nt][1]);
            *(float2*)&outp[(size_t)(r0 + 8) * C_DIM + n0 + cb] = make_float2(c[nt][2], c[nt][3]);
        }
    }
}

// ----------------------------------------------------------------------------
// Flash attention (causal) on mma.sync. CTA = (head, 128-row q tile), 8 warps.
// Warp owns 16 q rows. K tiles of 64 keys. Q/K hi+lo (3 MMAs), P/V hi+lo.
// K stored row-major [key][d]; V stored transposed [d][key] in smem.
// ----------------------------------------------------------------------------
__global__ __launch_bounds__(256) void attn_tc()
{
    __shared__ __nv_bfloat16 Kh[64 * SROW], Kl[64 * SROW];
    __shared__ __nv_bfloat16 Vh[64 * SROW], Vl[64 * SROW];

    const int h = blockIdx.y;
    const int qi = gridDim.x - 1 - blockIdx.x;   // long CTAs first
    const int q0 = qi * 128;
    const int tid = threadIdx.x;
    const int w = tid >> 5, lane = tid & 31;
    const int g = lane >> 2, t = lane & 3;

    const float* Qp = g_Q + (size_t)h * T_SEQ * HEAD_D;
    const float* Kp = g_K + (size_t)h * T_SEQ * HEAD_D;
    const float* Vp = g_V + (size_t)h * T_SEQ * HEAD_D;

    const int r0 = q0 + 16 * w + g;

    // Preload Q fragments (scaled by 1/sqrt(D)), hi/lo
    uint32_t qh[4][4], ql[4][4];
#pragma unroll
    for (int ks = 0; ks < 4; ks++) {
#pragma unroll
        for (int rr = 0; rr < 2; rr++) {
            const float* row = &Qp[(size_t)(r0 + 8 * rr) * HEAD_D];
            float2 v1 = *(const float2*)&row[16 * ks + 2 * t];
            float2 v2 = *(const float2*)&row[16 * ks + 2 * t + 8];
            split2(v1.x * 0.125f, v1.y * 0.125f, qh[ks][rr], ql[ks][rr]);
            split2(v2.x * 0.125f, v2.y * 0.125f, qh[ks][rr + 2], ql[ks][rr + 2]);
        }
    }

    float o[8][4];
#pragma unroll
    for (int i = 0; i < 8; i++)
#pragma unroll
        for (int j = 0; j < 4; j++) o[i][j] = 0.0f;
    float m_[2] = {-1e30f, -1e30f};
    float l_[2] = {0.0f, 0.0f};

    const int njt = 2 * qi + 2;
    for (int j = 0; j < njt; j++) {
        const int k0 = j * 64;
        // load K (row-major) and V (transposed), hi/lo
#pragma unroll
        for (int p = 0; p < 2; p++) {
            int r = p * 32 + (tid >> 3);
            int c0 = (tid & 7) * 8;
            float kv[8];
            const float4* s4 = (const float4*)&Kp[(size_t)(k0 + r) * HEAD_D + c0];
            *(float4*)&kv[0] = s4[0];
            *(float4*)&kv[4] = s4[1];
            uint4 hi, lo;
            split8(kv, hi, lo);
            *(uint4*)&Kh[r * SROW + c0] = hi;
            *(uint4*)&Kl[r * SROW + c0] = lo;

            float vv[8];
            const float4* v4 = (const float4*)&Vp[(size_t)(k0 + r) * HEAD_D + c0];
            *(float4*)&vv[0] = v4[0];
            *(float4*)&vv[4] = v4[1];
#pragma unroll
            for (int i = 0; i < 8; i++) {
                __nv_bfloat16 hb = __float2bfloat16(vv[i]);
                __nv_bfloat16 lb = __float2bfloat16(vv[i] - __bfloat162float(hb));
                Vh[(c0 + i) * SROW + r] = hb;
                Vl[(c0 + i) * SROW + r] = lb;
            }
        }
        __syncthreads();

        // S = Q K^T
        float s[8][4];
#pragma unroll
        for (int i = 0; i < 8; i++)
#pragma unroll
            for (int e = 0; e < 4; e++) s[i][e] = 0.0f;

#pragma unroll
        for (int ks = 0; ks < 4; ks++) {
#pragma unroll
            for (int nt = 0; nt < 8; nt++) {
                int kb = (8 * nt + g) * SROW + 16 * ks + 2 * t;
                uint32_t bh[2], bl[2];
                bh[0] = *(uint32_t*)&Kh[kb];
                bh[1] = *(uint32_t*)&Kh[kb + 8];
                bl[0] = *(uint32_t*)&Kl[kb];
                bl[1] = *(uint32_t*)&Kl[kb + 8];
                mma_bf16(s[nt], qh[ks], bh);
                mma_bf16(s[nt], qh[ks], bl);
                mma_bf16(s[nt], ql[ks], bh);
            }
        }

        // causal mask (only tiles overlapping the diagonal of this warp)
        if (k0 + 63 > q0 + 16 * w) {
#pragma unroll
            for (int nt = 0; nt < 8; nt++)
#pragma unroll
                for (int e = 0; e < 4; e++) {
                    int key = k0 + 8 * nt + 2 * t + (e & 1);
                    int row = r0 + 8 * (e >> 1);
                    if (key > row) s[nt][e] = -1e30f;
                }
        }

        // online softmax (rows g and g+8 per thread)
        float rmax0 = -1e30f, rmax1 = -1e30f;
#pragma unroll
        for (int nt = 0; nt < 8; nt++) {
            rmax0 = fmaxf(rmax0, fmaxf(s[nt][0], s[nt][1]));
            rmax1 = fmaxf(rmax1, fmaxf(s[nt][2], s[nt][3]));
        }
        rmax0 = fmaxf(rmax0, __shfl_xor_sync(0xffffffffu, rmax0, 1));
        rmax0 = fmaxf(rmax0, __shfl_xor_sync(0xffffffffu, rmax0, 2));
        rmax1 = fmaxf(rmax1, __shfl_xor_sync(0xffffffffu, rmax1, 1));
        rmax1 = fmaxf(rmax1, __shfl_xor_sync(0xffffffffu, rmax1, 2));

        float mn0 = fmaxf(m_[0], rmax0), mn1 = fmaxf(m_[1], rmax1);
        float corr0 = __expf(m_[0] - mn0), corr1 = __expf(m_[1] - mn1);
        float sum0 = 0.0f, sum1 = 0.0f;
#pragma unroll
        for (int nt = 0; nt < 8; nt++) {
            s[nt][0] = __expf(s[nt][0] - mn0);
            s[nt][1] = __expf(s[nt][1] - mn0);
            s[nt][2] = __expf(s[nt][2] - mn1);
            s[nt][3] = __expf(s[nt][3] - mn1);
            sum0 += s[nt][0] + s[nt][1];
            sum1 += s[nt][2] + s[nt][3];
        }
        sum0 += __shfl_xor_sync(0xffffffffu, sum0, 1);
        sum0 += __shfl_xor_sync(0xffffffffu, sum0, 2);
        sum1 += __shfl_xor_sync(0xffffffffu, sum1, 1);
        sum1 += __shfl_xor_sync(0xffffffffu, sum1, 2);
        l_[0] = l_[0] * corr0 + sum0;
        l_[1] = l_[1] * corr1 + sum1;
        m_[0] = mn0;
        m_[1] = mn1;
#pragma unroll
        for (int nt = 0; nt < 8; nt++) {
            o[nt][0] *= corr0;
            o[nt][1] *= corr0;
            o[nt][2] *= corr1;
            o[nt][3] *= corr1;
        }

        // O += P V   (P frags built in-register from S frag layout)
#pragma unroll
        for (int ks = 0; ks < 4; ks++) {
            uint32_t ph[4], pl[4];
            split2(s[2 * ks][0], s[2 * ks][1], ph[0], pl[0]);
            split2(s[2 * ks][2], s[2 * ks][3], ph[1], pl[1]);
            split2(s[2 * ks + 1][0], s[2 * ks + 1][1], ph[2], pl[2]);
            split2(s[2 * ks + 1][2], s[2 * ks + 1][3], ph[3], pl[3]);
#pragma unroll
            for (int nd = 0; nd < 8; nd++) {
                int vb = (8 * nd + g) * SROW + 16 * ks + 2 * t;
                uint32_t vh[2], vl[2];
                vh[0] = *(uint32_t*)&Vh[vb];
                vh[1] = *(uint32_t*)&Vh[vb + 8];
                vl[0] = *(uint32_t*)&Vl[vb];
                vl[1] = *(uint32_t*)&Vl[vb + 8];
                mma_bf16(o[nd], ph, vh);
                mma_bf16(o[nd], ph, vl);
                mma_bf16(o[nd], pl, vh);
            }
        }
        __syncthreads();
    }

    // normalize + write O in (T, C) layout
    float inv0 = 1.0f / l_[0], inv1 = 1.0f / l_[1];
#pragma unroll
    for (int nd = 0; nd < 8; nd++) {
        int col = h * HEAD_D + 8 * nd + 2 * t;
        *(float2*)&g_O[(size_t)r0 * C_DIM + col] =
            make_float2(o[nd][0] * inv0, o[nd][1] * inv0);
        *(float2*)&g_O[(size_t)(r0 + 8) * C_DIM + col] =
            make_float2(o[nd][2] * inv1, o[nd][3] * inv1);
    }
}

// ----------------------------------------------------------------------------
extern "C" void kernel_launch(void* const* d_in, const int* in_sizes, int n_in,
                              void* d_out, int out_size)
{
    const float* x  = (const float*)d_in[0];
    const float* wq = (const float*)d_in[1];
    const float* wk = (const float*)d_in[2];
    const float* wv = (const float*)d_in[3];
    const float* wo = (const float*)d_in[4];
    float* out = (float*)d_out;

    cudaFuncSetAttribute(gemm_tc<0>, cudaFuncAttributeMaxDynamicSharedMemorySize, GEMM_SMEM);
    cudaFuncSetAttribute(gemm_tc<1>, cudaFuncAttributeMaxDynamicSharedMemorySize, GEMM_SMEM);

    // 1) QKV projections
    gemm_tc<0><<<dim3(C_DIM / 64, T_SEQ / 128, 3), 256, GEMM_SMEM>>>(x, wq, wk, wv, nullptr);

    // 2) flash attention
    attn_tc<<<dim3(T_SEQ / 128, N_HEAD), 256>>>();

    // 3) output projection (wo in w0 slot — MODE 1 reads W = w0)
    gemm_tc<1><<<dim3(C_DIM / 64, T_SEQ / 128, 1), 256, GEMM_SMEM>>>(nullptr, wo, nullptr, nullptr, out);
}

// round 5
// speedup vs baseline: 3.3001x; 2.0498x over previous
#include <cuda_runtime.h>
#include <cuda_bf16.h>
#include <cstdint>
#include <math.h>

#define T_SEQ 4096
#define C_DIM 768
#define N_HEAD 12
#define HEAD_D 64
#define NW (C_DIM * C_DIM)
#define SROW 72   // smem row stride in bf16 (144B: conflict-free ldmatrix + cp.async)

// ----------------------------------------------------------------------------
// Device-global scratch (no allocation allowed)
// ----------------------------------------------------------------------------
__device__ __nv_bfloat16 g_Xh[T_SEQ * C_DIM], g_Xl[T_SEQ * C_DIM];
__device__ __nv_bfloat16 g_Wh[4 * NW], g_Wl[4 * NW];
__device__ __nv_bfloat16 g_Qh[N_HEAD * T_SEQ * HEAD_D], g_Ql[N_HEAD * T_SEQ * HEAD_D];
__device__ __nv_bfloat16 g_Kh[N_HEAD * T_SEQ * HEAD_D], g_Kl[N_HEAD * T_SEQ * HEAD_D];
__device__ __nv_bfloat16 g_Vh[N_HEAD * T_SEQ * HEAD_D], g_Vl[N_HEAD * T_SEQ * HEAD_D];
__device__ __nv_bfloat16 g_Oh[T_SEQ * C_DIM], g_Ol[T_SEQ * C_DIM];

// ----------------------------------------------------------------------------
// PTX helpers (baseline ISA only — plain sm_103 target)
// ----------------------------------------------------------------------------
__device__ __forceinline__ uint32_t smem_u32(const void* p) {
    uint32_t a;
    asm("{ .reg .u64 t; cvta.to.shared.u64 t, %1; cvt.u32.u64 %0, t; }"
        : "=r"(a) : "l"(p));
    return a;
}

__device__ __forceinline__ void mma_bf16(float* c, const uint32_t* a, const uint32_t* b) {
    asm volatile(
        "mma.sync.aligned.m16n8k16.row.col.f32.bf16.bf16.f32 "
        "{%0,%1,%2,%3}, {%4,%5,%6,%7}, {%8,%9}, {%0,%1,%2,%3};"
        : "+f"(c[0]), "+f"(c[1]), "+f"(c[2]), "+f"(c[3])
        : "r"(a[0]), "r"(a[1]), "r"(a[2]), "r"(a[3]), "r"(b[0]), "r"(b[1]));
}

#define LDSM4(r, a) \
    asm volatile("ldmatrix.sync.aligned.m8n8.x4.shared.b16 {%0,%1,%2,%3}, [%4];" \
        : "=r"((r)[0]), "=r"((r)[1]), "=r"((r)[2]), "=r"((r)[3]) : "r"(a))
#define LDSM4T(r, a) \
    asm volatile("ldmatrix.sync.aligned.m8n8.x4.trans.shared.b16 {%0,%1,%2,%3}, [%4];" \
        : "=r"((r)[0]), "=r"((r)[1]), "=r"((r)[2]), "=r"((r)[3]) : "r"(a))

#define CP16(dst, src) \
    asm volatile("cp.async.cg.shared.global [%0], [%1], 16;" :: "r"(dst), "l"(src))
#define CP_COMMIT() asm volatile("cp.async.commit_group;" ::: "memory")
__device__ __forceinline__ void cp_wait(bool deep) {
    if (deep) asm volatile("cp.async.wait_group 1;" ::: "memory");
    else      asm volatile("cp.async.wait_group 0;" ::: "memory");
}

__device__ __forceinline__ void split2(float x, float y, uint32_t& hi, uint32_t& lo) {
    __nv_bfloat162 h2 = __float22bfloat162_rn(make_float2(x, y));
    float rx = x - __bfloat162float(h2.x);
    float ry = y - __bfloat162float(h2.y);
    __nv_bfloat162 l2 = __float22bfloat162_rn(make_float2(rx, ry));
    hi = *reinterpret_cast<uint32_t*>(&h2);
    lo = *reinterpret_cast<uint32_t*>(&l2);
}

// ----------------------------------------------------------------------------
// Pre-convert x and weights to bf16 hi/lo (one pass, memory-bound)
// ----------------------------------------------------------------------------
#define NX4 (T_SEQ * C_DIM / 4)
#define NW4 (NW / 4)
#define NCONV (NX4 + 4 * NW4)

__global__ __launch_bounds__(256) void convert_kernel(
    const float* __restrict__ x,  const float* __restrict__ wq,
    const float* __restrict__ wk, const float* __restrict__ wv,
    const float* __restrict__ wo)
{
    int i = blockIdx.x * 256 + threadIdx.x;
    if (i >= NCONV) return;
    const float* src;
    __nv_bfloat16 *dh, *dl;
    size_t off;
    if (i < NX4) {
        src = x; off = i; dh = g_Xh; dl = g_Xl;
    } else {
        int wi = (i - NX4) / NW4;
        off = (i - NX4) % NW4;
        src = (wi == 0) ? wq : (wi == 1) ? wk : (wi == 2) ? wv : wo;
        dh = g_Wh + (size_t)wi * NW;
        dl = g_Wl + (size_t)wi * NW;
    }
    float4 v = ((const float4*)src)[off];
    uint32_t h0, l0, h1, l1;
    split2(v.x, v.y, h0, l0);
    split2(v.z, v.w, h1, l1);
    ((uint2*)dh)[off] = make_uint2(h0, h1);
    ((uint2*)dl)[off] = make_uint2(l0, l1);
}

// ----------------------------------------------------------------------------
// GEMM C[M,N] = A @ W^T, bf16 hi/lo inputs (3-MMA combo), cp.async 2-stage.
// CTA 128x64, 8 warps (warp: 16 rows x 64 cols), K-chunk 64.
// MODE 0: A=g_X*, W=g_W*[z] -> writes g_Q/K/V hi/lo (Q scaled 0.125)
// MODE 1: A=g_O*, W=g_W*[3] -> writes fp32 out
// ----------------------------------------------------------------------------
#define G_STG 27648                 // stage elems: (128+128+64+64)*72
#define G_AH 0
#define G_AL 9216
#define G_BH 18432
#define G_BL 23040
static constexpr int GEMM_SMEM = 2 * G_STG * 2;  // 110592 B

template <int MODE>
__global__ __launch_bounds__(256) void gemm_bf(float* __restrict__ outp)
{
    extern __shared__ __nv_bfloat16 sb[];
    const uint32_t sbase = smem_u32(sb);
    const int tid = threadIdx.x;
    const int w = tid >> 5, lane = tid & 31;
    const int g = lane >> 2, t = lane & 3;
    const int sub = lane >> 3, rrow = lane & 7;
    const int m0 = blockIdx.y * 128, n0 = blockIdx.x * 64;
    const int z = (MODE == 0) ? blockIdx.z : 3;

    const __nv_bfloat16* Ah = (MODE == 0) ? g_Xh : g_Oh;
    const __nv_bfloat16* Al = (MODE == 0) ? g_Xl : g_Ol;
    const __nv_bfloat16* Bh = g_Wh + (size_t)z * NW;
    const __nv_bfloat16* Bl = g_Wl + (size_t)z * NW;

    float c[8][4];
#pragma unroll
    for (int i = 0; i < 8; i++)
#pragma unroll
        for (int j = 0; j < 4; j++) c[i][j] = 0.0f;

    auto load_stage = [&](int s, int ch) {
        const int k0 = ch * 64;
        const uint32_t se = s * G_STG;
#pragma unroll
        for (int p = 0; p < 4; p++) {
            int slot = tid + p * 256;
            int r = slot >> 3, cc = (slot & 7) * 8;
            CP16(sbase + (se + G_AH + r * SROW + cc) * 2,
                 &Ah[(size_t)(m0 + r) * C_DIM + k0 + cc]);
            CP16(sbase + (se + G_AL + r * SROW + cc) * 2,
                 &Al[(size_t)(m0 + r) * C_DIM + k0 + cc]);
        }
#pragma unroll
        for (int p = 0; p < 2; p++) {
            int slot = tid + p * 256;
            int r = slot >> 3, cc = (slot & 7) * 8;
            CP16(sbase + (se + G_BH + r * SROW + cc) * 2,
                 &Bh[(size_t)(n0 + r) * C_DIM + k0 + cc]);
            CP16(sbase + (se + G_BL + r * SROW + cc) * 2,
                 &Bl[(size_t)(n0 + r) * C_DIM + k0 + cc]);
        }
        CP_COMMIT();
    };

    load_stage(0, 0);
    const int NCH = C_DIM / 64;
    for (int ch = 0; ch < NCH; ch++) {
        bool more = (ch + 1 < NCH);
        if (more) load_stage((ch + 1) & 1, ch + 1);
        cp_wait(more);
        __syncthreads();
        const uint32_t se = (ch & 1) * G_STG;
#pragma unroll
        for (int ks = 0; ks < 4; ks++) {
            uint32_t ah[4], al[4];
            uint32_t aaddr = sbase + (se + G_AH +
                (16 * w + (sub & 1) * 8 + rrow) * SROW + 16 * ks + (sub >> 1) * 8) * 2;
            LDSM4(ah, aaddr);
            LDSM4(al, aaddr + (G_AL - G_AH) * 2);
#pragma unroll
            for (int p = 0; p < 4; p++) {
                uint32_t bh[4], bl[4];
                uint32_t baddr = sbase + (se + G_BH +
                    (16 * p + (sub >> 1) * 8 + rrow) * SROW + 16 * ks + (sub & 1) * 8) * 2;
                LDSM4(bh, baddr);
                LDSM4(bl, baddr + (G_BL - G_BH) * 2);
                mma_bf16(c[2 * p], ah, bh);
                mma_bf16(c[2 * p], ah, bl);
                mma_bf16(c[2 * p], al, bh);
                mma_bf16(c[2 * p + 1], ah, bh + 2);
                mma_bf16(c[2 * p + 1], ah, bl + 2);
                mma_bf16(c[2 * p + 1], al, bh + 2);
            }
        }
        __syncthreads();
    }

    const int r0 = m0 + 16 * w + g;
    if (MODE == 0) {
        __nv_bfloat16* dh = (z == 0) ? g_Qh : (z == 1) ? g_Kh : g_Vh;
        __nv_bfloat16* dl = (z == 0) ? g_Ql : (z == 1) ? g_Kl : g_Vl;
        const float sc = (z == 0) ? 0.125f : 1.0f;
        const int head = blockIdx.x;
#pragma unroll
        for (int nt = 0; nt < 8; nt++) {
            int cb = 8 * nt + 2 * t;
            uint32_t h0, l0, h1, l1;
            split2(c[nt][0] * sc, c[nt][1] * sc, h0, l0);
            split2(c[nt][2] * sc, c[nt][3] * sc, h1, l1);
            size_t o1 = ((size_t)head * T_SEQ + r0) * HEAD_D + cb;
            size_t o2 = ((size_t)head * T_SEQ + r0 + 8) * HEAD_D + cb;
            *(uint32_t*)&dh[o1] = h0; *(uint32_t*)&dl[o1] = l0;
            *(uint32_t*)&dh[o2] = h1; *(uint32_t*)&dl[o2] = l1;
        }
    } else {
#pragma unroll
        for (int nt = 0; nt < 8; nt++) {
            int cb = 8 * nt + 2 * t;
            *(float2*)&outp[(size_t)r0 * C_DIM + n0 + cb] = make_float2(c[nt][0], c[nt][1]);
            *(float2*)&outp[(size_t)(r0 + 8) * C_DIM + n0 + cb] = make_float2(c[nt][2], c[nt][3]);
        }
    }
}

// ----------------------------------------------------------------------------
// Flash attention (causal), all-bf16 hi/lo, cp.async 2-stage, ldmatrix frags.
// CTA = (head, 128 q rows), 8 warps (warp: 16 rows). K-tile 64 keys.
// ----------------------------------------------------------------------------
#define A_STG 18432                 // stage elems: 4*64*72
#define A_KH 0
#define A_KL 4608
#define A_VH 9216
#define A_VL 13824
static constexpr int ATTN_SMEM = 2 * A_STG * 2;  // 73728 B

__global__ __launch_bounds__(256) void attn_bf()
{
    extern __shared__ __nv_bfloat16 sa[];
    const uint32_t sbase = smem_u32(sa);
    const int h = blockIdx.y;
    const int qi = gridDim.x - 1 - blockIdx.x;   // long CTAs first
    const int q0 = qi * 128;
    const int tid = threadIdx.x;
    const int w = tid >> 5, lane = tid & 31;
    const int g = lane >> 2, t = lane & 3;
    const int sub = lane >> 3, rrow = lane & 7;

    const __nv_bfloat16* Qhp = g_Qh + (size_t)h * T_SEQ * HEAD_D;
    const __nv_bfloat16* Qlp = g_Ql + (size_t)h * T_SEQ * HEAD_D;
    const __nv_bfloat16* Khp = g_Kh + (size_t)h * T_SEQ * HEAD_D;
    const __nv_bfloat16* Klp = g_Kl + (size_t)h * T_SEQ * HEAD_D;
    const __nv_bfloat16* Vhp = g_Vh + (size_t)h * T_SEQ * HEAD_D;
    const __nv_bfloat16* Vlp = g_Vl + (size_t)h * T_SEQ * HEAD_D;

    const int r0 = q0 + 16 * w + g;

    // Q fragments from gmem (already scaled by 1/8)
    uint32_t qh[4][4], ql[4][4];
#pragma unroll
    for (int ks = 0; ks < 4; ks++) {
#pragma unroll
        for (int rr = 0; rr < 2; rr++) {
            size_t base = (size_t)(r0 + 8 * rr) * HEAD_D + 16 * ks + 2 * t;
            qh[ks][rr]     = *(const uint32_t*)&Qhp[base];
            qh[ks][rr + 2] = *(const uint32_t*)&Qhp[base + 8];
            ql[ks][rr]     = *(const uint32_t*)&Qlp[base];
            ql[ks][rr + 2] = *(const uint32_t*)&Qlp[base + 8];
        }
    }

    float o[8][4];
#pragma unroll
    for (int i = 0; i < 8; i++)
#pragma unroll
        for (int j = 0; j < 4; j++) o[i][j] = 0.0f;
    float m_[2] = {-1e30f, -1e30f};
    float l_[2] = {0.0f, 0.0f};

    auto load_stage = [&](int s, int j) {
        const int k0 = j * 64;
        const uint32_t se = s * A_STG;
#pragma unroll
        for (int p = 0; p < 2; p++) {
            int slot = tid + p * 256;
            int r = slot >> 3, cc = (slot & 7) * 8;
            size_t go = (size_t)(k0 + r) * HEAD_D + cc;
            uint32_t so = (se + r * SROW + cc) * 2;
            CP16(sbase + so + A_KH * 2, &Khp[go]);
            CP16(sbase + so + A_KL * 2, &Klp[go]);
            CP16(sbase + so + A_VH * 2, &Vhp[go]);
            CP16(sbase + so + A_VL * 2, &Vlp[go]);
        }
        CP_COMMIT();
    };

    const int njt = 2 * qi + 2;
    load_stage(0, 0);
    for (int j = 0; j < njt; j++) {
        bool more = (j + 1 < njt);
        if (more) load_stage((j + 1) & 1, j + 1);
        cp_wait(more);
        __syncthreads();

        const int k0 = j * 64;
        const uint32_t se = (j & 1) * A_STG;
        const bool active = (k0 <= q0 + 16 * w + 15);

        if (active) {
            // S = Q K^T
            float s[8][4];
#pragma unroll
            for (int i = 0; i < 8; i++)
#pragma unroll
                for (int e = 0; e < 4; e++) s[i][e] = 0.0f;

#pragma unroll
            for (int ks = 0; ks < 4; ks++) {
#pragma unroll
                for (int p = 0; p < 4; p++) {
                    uint32_t bh[4], bl[4];
                    uint32_t kaddr = sbase + (se + A_KH +
                        (16 * p + (sub >> 1) * 8 + rrow) * SROW + 16 * ks + (sub & 1) * 8) * 2;
                    LDSM4(bh, kaddr);
                    LDSM4(bl, kaddr + (A_KL - A_KH) * 2);
                    mma_bf16(s[2 * p], qh[ks], bh);
                    mma_bf16(s[2 * p], qh[ks], bl);
                    mma_bf16(s[2 * p], ql[ks], bh);
                    mma_bf16(s[2 * p + 1], qh[ks], bh + 2);
                    mma_bf16(s[2 * p + 1], qh[ks], bl + 2);
                    mma_bf16(s[2 * p + 1], ql[ks], bh + 2);
                }
            }

            // causal mask (only tiles crossing this warp's diagonal)
            if (k0 + 63 > q0 + 16 * w) {
#pragma unroll
                for (int nt = 0; nt < 8; nt++)
#pragma unroll
                    for (int e = 0; e < 4; e++) {
                        int key = k0 + 8 * nt + 2 * t + (e & 1);
                        int row = r0 + 8 * (e >> 1);
                        if (key > row) s[nt][e] = -1e30f;
                    }
            }

            // online softmax (rows g, g+8)
            float rmax0 = -1e30f, rmax1 = -1e30f;
#pragma unroll
            for (int nt = 0; nt < 8; nt++) {
                rmax0 = fmaxf(rmax0, fmaxf(s[nt][0], s[nt][1]));
                rmax1 = fmaxf(rmax1, fmaxf(s[nt][2], s[nt][3]));
            }
            rmax0 = fmaxf(rmax0, __shfl_xor_sync(0xffffffffu, rmax0, 1));
            rmax0 = fmaxf(rmax0, __shfl_xor_sync(0xffffffffu, rmax0, 2));
            rmax1 = fmaxf(rmax1, __shfl_xor_sync(0xffffffffu, rmax1, 1));
            rmax1 = fmaxf(rmax1, __shfl_xor_sync(0xffffffffu, rmax1, 2));

            float mn0 = fmaxf(m_[0], rmax0), mn1 = fmaxf(m_[1], rmax1);
            float corr0 = __expf(m_[0] - mn0), corr1 = __expf(m_[1] - mn1);
            float sum0 = 0.0f, sum1 = 0.0f;
#pragma unroll
            for (int nt = 0; nt < 8; nt++) {
                s[nt][0] = __expf(s[nt][0] - mn0);
                s[nt][1] = __expf(s[nt][1] - mn0);
                s[nt][2] = __expf(s[nt][2] - mn1);
                s[nt][3] = __expf(s[nt][3] - mn1);
                sum0 += s[nt][0] + s[nt][1];
                sum1 += s[nt][2] + s[nt][3];
            }
            sum0 += __shfl_xor_sync(0xffffffffu, sum0, 1);
            sum0 += __shfl_xor_sync(0xffffffffu, sum0, 2);
            sum1 += __shfl_xor_sync(0xffffffffu, sum1, 1);
            sum1 += __shfl_xor_sync(0xffffffffu, sum1, 2);
            l_[0] = l_[0] * corr0 + sum0;
            l_[1] = l_[1] * corr1 + sum1;
            m_[0] = mn0;
            m_[1] = mn1;
#pragma unroll
            for (int nt = 0; nt < 8; nt++) {
                o[nt][0] *= corr0;
                o[nt][1] *= corr0;
                o[nt][2] *= corr1;
                o[nt][3] *= corr1;
            }

            // O += P V  (P hi/lo in-register; V frags via ldmatrix.trans)
#pragma unroll
            for (int ks = 0; ks < 4; ks++) {
                uint32_t ph[4], pl[4];
                split2(s[2 * ks][0],     s[2 * ks][1],     ph[0], pl[0]);
                split2(s[2 * ks][2],     s[2 * ks][3],     ph[1], pl[1]);
                split2(s[2 * ks + 1][0], s[2 * ks + 1][1], ph[2], pl[2]);
                split2(s[2 * ks + 1][2], s[2 * ks + 1][3], ph[3], pl[3]);
#pragma unroll
                for (int p = 0; p < 4; p++) {
                    uint32_t vh[4], vl[4];
                    uint32_t vaddr = sbase + (se + A_VH +
                        (16 * ks + (sub & 1) * 8 + rrow) * SROW + 16 * p + (sub >> 1) * 8) * 2;
                    LDSM4T(vh, vaddr);
                    LDSM4T(vl, vaddr + (A_VL - A_VH) * 2);
                    mma_bf16(o[2 * p], ph, vh);
                    mma_bf16(o[2 * p], ph, vl);
                    mma_bf16(o[2 * p], pl, vh);
                    mma_bf16(o[2 * p + 1], ph, vh + 2);
                    mma_bf16(o[2 * p + 1], ph, vl + 2);
                    mma_bf16(o[2 * p + 1], pl, vh + 2);
                }
            }
        }
        __syncthreads();
    }

    // normalize + write O as bf16 hi/lo in (T, C) layout
    float inv0 = 1.0f / l_[0], inv1 = 1.0f / l_[1];
#pragma unroll
    for (int nd = 0; nd < 8; nd++) {
        int col = h * HEAD_D + 8 * nd + 2 * t;
        uint32_t h0, l0, h1, l1;
        split2(o[nd][0] * inv0, o[nd][1] * inv0, h0, l0);
        split2(o[nd][2] * inv1, o[nd][3] * inv1, h1, l1);
        size_t o1 = (size_t)r0 * C_DIM + col;
        size_t o2 = (size_t)(r0 + 8) * C_DIM + col;
        *(uint32_t*)&g_Oh[o1] = h0; *(uint32_t*)&g_Ol[o1] = l0;
        *(uint32_t*)&g_Oh[o2] = h1; *(uint32_t*)&g_Ol[o2] = l1;
    }
}

// ----------------------------------------------------------------------------
extern "C" void kernel_launch(void* const* d_in, const int* in_sizes, int n_in,
                              void* d_out, int out_size)
{
    const float* x  = (const float*)d_in[0];
    const float* wq = (const float*)d_in[1];
    const float* wk = (const float*)d_in[2];
    const float* wv = (const float*)d_in[3];
    const float* wo = (const float*)d_in[4];
    float* out = (float*)d_out;

    cudaFuncSetAttribute(gemm_bf<0>, cudaFuncAttributeMaxDynamicSharedMemorySize, GEMM_SMEM);
    cudaFuncSetAttribute(gemm_bf<1>, cudaFuncAttributeMaxDynamicSharedMemorySize, GEMM_SMEM);
    cudaFuncSetAttribute(attn_bf, cudaFuncAttributeMaxDynamicSharedMemorySize, ATTN_SMEM);

    // 0) one-time hi/lo conversion of x and weights
    convert_kernel<<<(NCONV + 255) / 256, 256>>>(x, wq, wk, wv, wo);

    // 1) QKV projections (writes bf16 hi/lo Q(scaled)/K/V)
    gemm_bf<0><<<dim3(C_DIM / 64, T_SEQ / 128, 3), 256, GEMM_SMEM>>>(nullptr);

    // 2) flash attention (writes bf16 hi/lo O)
    attn_bf<<<dim3(T_SEQ / 128, N_HEAD), 256, ATTN_SMEM>>>();

    // 3) output projection -> fp32 out
    gemm_bf<1><<<dim3(C_DIM / 64, T_SEQ / 128, 1), 256, GEMM_SMEM>>>(out);
}

// round 6
// speedup vs baseline: 4.5727x; 1.3856x over previous
#include <cuda_runtime.h>
#include <cuda_fp16.h>
#include <cstdint>
#include <math.h>

#define T_SEQ 4096
#define C_DIM 768
#define N_HEAD 12
#define HEAD_D 64
#define NW (C_DIM * C_DIM)
#define SROW 72   // smem row stride in halves (144B: conflict-free ldmatrix + cp.async)

// ----------------------------------------------------------------------------
// Device-global scratch (no allocation allowed)
// A-side operands keep hi/lo; B-side operands (W, K, V) are fp16-rounded only.
// ----------------------------------------------------------------------------
__device__ __half g_Xh[T_SEQ * C_DIM], g_Xl[T_SEQ * C_DIM];
__device__ __half g_Wh[4 * NW];
__device__ __half g_Qh[N_HEAD * T_SEQ * HEAD_D], g_Ql[N_HEAD * T_SEQ * HEAD_D];
__device__ __half g_Kh[N_HEAD * T_SEQ * HEAD_D];
__device__ __half g_Vh[N_HEAD * T_SEQ * HEAD_D];
__device__ __half g_Oh[T_SEQ * C_DIM], g_Ol[T_SEQ * C_DIM];

// ----------------------------------------------------------------------------
// PTX helpers (baseline ISA only — plain sm_103 target)
// ----------------------------------------------------------------------------
__device__ __forceinline__ uint32_t smem_u32(const void* p) {
    uint32_t a;
    asm("{ .reg .u64 t; cvta.to.shared.u64 t, %1; cvt.u32.u64 %0, t; }"
        : "=r"(a) : "l"(p));
    return a;
}

__device__ __forceinline__ void mma_f16(float* c, const uint32_t* a, const uint32_t* b) {
    asm volatile(
        "mma.sync.aligned.m16n8k16.row.col.f32.f16.f16.f32 "
        "{%0,%1,%2,%3}, {%4,%5,%6,%7}, {%8,%9}, {%0,%1,%2,%3};"
        : "+f"(c[0]), "+f"(c[1]), "+f"(c[2]), "+f"(c[3])
        : "r"(a[0]), "r"(a[1]), "r"(a[2]), "r"(a[3]), "r"(b[0]), "r"(b[1]));
}

#define LDSM4(r, a) \
    asm volatile("ldmatrix.sync.aligned.m8n8.x4.shared.b16 {%0,%1,%2,%3}, [%4];" \
        : "=r"((r)[0]), "=r"((r)[1]), "=r"((r)[2]), "=r"((r)[3]) : "r"(a))
#define LDSM4T(r, a) \
    asm volatile("ldmatrix.sync.aligned.m8n8.x4.trans.shared.b16 {%0,%1,%2,%3}, [%4];" \
        : "=r"((r)[0]), "=r"((r)[1]), "=r"((r)[2]), "=r"((r)[3]) : "r"(a))

#define CP16(dst, src) \
    asm volatile("cp.async.cg.shared.global [%0], [%1], 16;" :: "r"(dst), "l"(src))
#define CP_COMMIT() asm volatile("cp.async.commit_group;" ::: "memory")
#define CP_WAIT0() asm volatile("cp.async.wait_group 0;" ::: "memory")
#define CP_WAIT1() asm volatile("cp.async.wait_group 1;" ::: "memory")

__device__ __forceinline__ uint32_t pack_h2(float x, float y) {
    __half2 h = __float22half2_rn(make_float2(x, y));
    return *reinterpret_cast<uint32_t*>(&h);
}

// fp16 hi + residual-lo split of a float pair
__device__ __forceinline__ void split2(float x, float y, uint32_t& hi, uint32_t& lo) {
    __half2 h2 = __float22half2_rn(make_float2(x, y));
    float2 hf = __half22float2(h2);
    __half2 l2 = __float22half2_rn(make_float2(x - hf.x, y - hf.y));
    hi = *reinterpret_cast<uint32_t*>(&h2);
    lo = *reinterpret_cast<uint32_t*>(&l2);
}

// ----------------------------------------------------------------------------
// Pre-convert: x -> fp16 hi/lo ; weights -> fp16 hi only
// ----------------------------------------------------------------------------
#define NX4 (T_SEQ * C_DIM / 4)
#define NW4 (NW / 4)
#define NCONV (NX4 + 4 * NW4)

__global__ __launch_bounds__(256) void convert_kernel(
    const float* __restrict__ x,  const float* __restrict__ wq,
    const float* __restrict__ wk, const float* __restrict__ wv,
    const float* __restrict__ wo)
{
    int i = blockIdx.x * 256 + threadIdx.x;
    if (i >= NCONV) return;
    if (i < NX4) {
        float4 v = ((const float4*)x)[i];
        uint32_t h0, l0, h1, l1;
        split2(v.x, v.y, h0, l0);
        split2(v.z, v.w, h1, l1);
        ((uint2*)g_Xh)[i] = make_uint2(h0, h1);
        ((uint2*)g_Xl)[i] = make_uint2(l0, l1);
    } else {
        int wi = (i - NX4) / NW4;
        size_t off = (i - NX4) % NW4;
        const float* src = (wi == 0) ? wq : (wi == 1) ? wk : (wi == 2) ? wv : wo;
        float4 v = ((const float4*)src)[off];
        ((uint2*)(g_Wh + (size_t)wi * NW))[off] =
            make_uint2(pack_h2(v.x, v.y), pack_h2(v.z, v.w));
    }
}

// ----------------------------------------------------------------------------
// GEMM C[M,N] = A @ W^T; A fp16 hi/lo (2-MMA compensation), W fp16.
// CTA 128x64, 8 warps (warp: 16 rows), K-chunk 64, 2-stage cp.async.
// MODE 0: A=g_X*, W=g_Wh[z] -> Q hi/lo (unscaled) / K hi / V hi
// MODE 1: A=g_O*, W=g_Wh[3] -> fp32 out
// ----------------------------------------------------------------------------
#define G_AH 0
#define G_AL 9216
#define G_BH 18432
#define G_STG 23040
static constexpr int GEMM_SMEM = 2 * G_STG * 2;  // 92160 B

template <int MODE>
__global__ __launch_bounds__(256) void gemm_hf(float* __restrict__ outp)
{
    extern __shared__ __half sb[];
    const uint32_t sbase = smem_u32(sb);
    const int tid = threadIdx.x;
    const int w = tid >> 5, lane = tid & 31;
    const int g = lane >> 2, t = lane & 3;
    const int sub = lane >> 3, rrow = lane & 7;
    const int m0 = blockIdx.y * 128, n0 = blockIdx.x * 64;
    const int z = (MODE == 0) ? blockIdx.z : 3;

    const __half* Ah = (MODE == 0) ? g_Xh : g_Oh;
    const __half* Al = (MODE == 0) ? g_Xl : g_Ol;
    const __half* Bh = g_Wh + (size_t)z * NW;

    float c[8][4];
#pragma unroll
    for (int i = 0; i < 8; i++)
#pragma unroll
        for (int j = 0; j < 4; j++) c[i][j] = 0.0f;

    auto load_stage = [&](int s, int ch) {
        const int k0 = ch * 64;
        const uint32_t se = s * G_STG;
#pragma unroll
        for (int p = 0; p < 4; p++) {
            int slot = tid + p * 256;
            int r = slot >> 3, cc = (slot & 7) * 8;
            CP16(sbase + (se + G_AH + r * SROW + cc) * 2,
                 &Ah[(size_t)(m0 + r) * C_DIM + k0 + cc]);
            CP16(sbase + (se + G_AL + r * SROW + cc) * 2,
                 &Al[(size_t)(m0 + r) * C_DIM + k0 + cc]);
        }
#pragma unroll
        for (int p = 0; p < 2; p++) {
            int slot = tid + p * 256;
            int r = slot >> 3, cc = (slot & 7) * 8;
            CP16(sbase + (se + G_BH + r * SROW + cc) * 2,
                 &Bh[(size_t)(n0 + r) * C_DIM + k0 + cc]);
        }
        CP_COMMIT();
    };

    load_stage(0, 0);
    const int NCH = C_DIM / 64;
    for (int ch = 0; ch < NCH; ch++) {
        bool more = (ch + 1 < NCH);
        if (more) load_stage((ch + 1) & 1, ch + 1);
        if (more) CP_WAIT1(); else CP_WAIT0();
        __syncthreads();
        const uint32_t se = (ch & 1) * G_STG;
#pragma unroll
        for (int ks = 0; ks < 4; ks++) {
            uint32_t ah[4], al[4];
            uint32_t aaddr = sbase + (se + G_AH +
                (16 * w + (sub & 1) * 8 + rrow) * SROW + 16 * ks + (sub >> 1) * 8) * 2;
            LDSM4(ah, aaddr);
            LDSM4(al, aaddr + (G_AL - G_AH) * 2);
#pragma unroll
            for (int p = 0; p < 4; p++) {
                uint32_t bh[4];
                uint32_t baddr = sbase + (se + G_BH +
                    (16 * p + (sub >> 1) * 8 + rrow) * SROW + 16 * ks + (sub & 1) * 8) * 2;
                LDSM4(bh, baddr);
                mma_f16(c[2 * p], ah, bh);
                mma_f16(c[2 * p], al, bh);
                mma_f16(c[2 * p + 1], ah, bh + 2);
                mma_f16(c[2 * p + 1], al, bh + 2);
            }
        }
        __syncthreads();
    }

    const int r0 = m0 + 16 * w + g;
    if (MODE == 0) {
        const int head = blockIdx.x;
        if (z == 0) {
#pragma unroll
            for (int nt = 0; nt < 8; nt++) {
                int cb = 8 * nt + 2 * t;
                uint32_t h0, l0, h1, l1;
                split2(c[nt][0], c[nt][1], h0, l0);
                split2(c[nt][2], c[nt][3], h1, l1);
                size_t o1 = ((size_t)head * T_SEQ + r0) * HEAD_D + cb;
                size_t o2 = ((size_t)head * T_SEQ + r0 + 8) * HEAD_D + cb;
                *(uint32_t*)&g_Qh[o1] = h0; *(uint32_t*)&g_Ql[o1] = l0;
                *(uint32_t*)&g_Qh[o2] = h1; *(uint32_t*)&g_Ql[o2] = l1;
            }
        } else {
            __half* dh = (z == 1) ? g_Kh : g_Vh;
#pragma unroll
            for (int nt = 0; nt < 8; nt++) {
                int cb = 8 * nt + 2 * t;
                size_t o1 = ((size_t)head * T_SEQ + r0) * HEAD_D + cb;
                size_t o2 = ((size_t)head * T_SEQ + r0 + 8) * HEAD_D + cb;
                *(uint32_t*)&dh[o1] = pack_h2(c[nt][0], c[nt][1]);
                *(uint32_t*)&dh[o2] = pack_h2(c[nt][2], c[nt][3]);
            }
        }
    } else {
#pragma unroll
        for (int nt = 0; nt < 8; nt++) {
            int cb = 8 * nt + 2 * t;
            *(float2*)&outp[(size_t)r0 * C_DIM + n0 + cb] = make_float2(c[nt][0], c[nt][1]);
            *(float2*)&outp[(size_t)(r0 + 8) * C_DIM + n0 + cb] = make_float2(c[nt][2], c[nt][3]);
        }
    }
}

// ----------------------------------------------------------------------------
// Flash attention (causal): Q hi/lo x K (2 MMA), P hi/lo x V (2 MMA).
// CTA = (head, 128 q rows), 8 warps; 64-key tiles; 3-stage cp.async pipeline.
// ----------------------------------------------------------------------------
#define A_KH 0
#define A_VH 4608
#define A_STG 9216
static constexpr int ATTN_SMEM = 3 * A_STG * 2;  // 55296 B

__global__ __launch_bounds__(256) void attn_hf()
{
    extern __shared__ __half sa[];
    const uint32_t sbase = smem_u32(sa);
    const int h = blockIdx.y;
    const int qi = gridDim.x - 1 - blockIdx.x;   // long CTAs first
    const int q0 = qi * 128;
    const int tid = threadIdx.x;
    const int w = tid >> 5, lane = tid & 31;
    const int g = lane >> 2, t = lane & 3;
    const int sub = lane >> 3, rrow = lane & 7;

    const __half* Qhp = g_Qh + (size_t)h * T_SEQ * HEAD_D;
    const __half* Qlp = g_Ql + (size_t)h * T_SEQ * HEAD_D;
    const __half* Khp = g_Kh + (size_t)h * T_SEQ * HEAD_D;
    const __half* Vhp = g_Vh + (size_t)h * T_SEQ * HEAD_D;

    const int r0 = q0 + 16 * w + g;

    uint32_t qh[4][4], ql[4][4];
#pragma unroll
    for (int ks = 0; ks < 4; ks++) {
#pragma unroll
        for (int rr = 0; rr < 2; rr++) {
            size_t base = (size_t)(r0 + 8 * rr) * HEAD_D + 16 * ks + 2 * t;
            qh[ks][rr]     = *(const uint32_t*)&Qhp[base];
            qh[ks][rr + 2] = *(const uint32_t*)&Qhp[base + 8];
            ql[ks][rr]     = *(const uint32_t*)&Qlp[base];
            ql[ks][rr + 2] = *(const uint32_t*)&Qlp[base + 8];
        }
    }

    float o[8][4];
#pragma unroll
    for (int i = 0; i < 8; i++)
#pragma unroll
        for (int j = 0; j < 4; j++) o[i][j] = 0.0f;
    float m_[2] = {-1e30f, -1e30f};
    float l_[2] = {0.0f, 0.0f};

    auto load_stage = [&](int j) {
        const int k0 = j * 64;
        const uint32_t se = (j % 3) * A_STG;
#pragma unroll
        for (int p = 0; p < 2; p++) {
            int slot = tid + p * 256;
            int r = slot >> 3, cc = (slot & 7) * 8;
            size_t go = (size_t)(k0 + r) * HEAD_D + cc;
            uint32_t so = (se + r * SROW + cc) * 2;
            CP16(sbase + so + A_KH * 2, &Khp[go]);
            CP16(sbase + so + A_VH * 2, &Vhp[go]);
        }
        CP_COMMIT();
    };

    const int njt = 2 * qi + 2;
    load_stage(0);
    load_stage(1);
    for (int j = 0; j < njt; j++) {
        if (j + 1 < njt) CP_WAIT1(); else CP_WAIT0();
        __syncthreads();
        if (j + 2 < njt) load_stage(j + 2);

        const int k0 = j * 64;
        const uint32_t se = (j % 3) * A_STG;
        const bool active = (k0 <= q0 + 16 * w + 15);

        if (active) {
            float s[8][4];
#pragma unroll
            for (int i = 0; i < 8; i++)
#pragma unroll
                for (int e = 0; e < 4; e++) s[i][e] = 0.0f;

            // S = Q K^T  (Q hi/lo compensated, K rounded)
#pragma unroll
            for (int ks = 0; ks < 4; ks++) {
#pragma unroll
                for (int p = 0; p < 4; p++) {
                    uint32_t kh[4];
                    uint32_t kaddr = sbase + (se + A_KH +
                        (16 * p + (sub >> 1) * 8 + rrow) * SROW + 16 * ks + (sub & 1) * 8) * 2;
                    LDSM4(kh, kaddr);
                    mma_f16(s[2 * p], qh[ks], kh);
                    mma_f16(s[2 * p], ql[ks], kh);
                    mma_f16(s[2 * p + 1], qh[ks], kh + 2);
                    mma_f16(s[2 * p + 1], ql[ks], kh + 2);
                }
            }

            // scale + causal mask
#pragma unroll
            for (int nt = 0; nt < 8; nt++)
#pragma unroll
                for (int e = 0; e < 4; e++) s[nt][e] *= 0.125f;
            if (k0 + 63 > q0 + 16 * w) {
#pragma unroll
                for (int nt = 0; nt < 8; nt++)
#pragma unroll
                    for (int e = 0; e < 4; e++) {
                        int key = k0 + 8 * nt + 2 * t + (e & 1);
                        int row = r0 + 8 * (e >> 1);
                        if (key > row) s[nt][e] = -1e30f;
                    }
            }

            // online softmax (rows g, g+8)
            float rmax0 = -1e30f, rmax1 = -1e30f;
#pragma unroll
            for (int nt = 0; nt < 8; nt++) {
                rmax0 = fmaxf(rmax0, fmaxf(s[nt][0], s[nt][1]));
                rmax1 = fmaxf(rmax1, fmaxf(s[nt][2], s[nt][3]));
            }
            rmax0 = fmaxf(rmax0, __shfl_xor_sync(0xffffffffu, rmax0, 1));
            rmax0 = fmaxf(rmax0, __shfl_xor_sync(0xffffffffu, rmax0, 2));
            rmax1 = fmaxf(rmax1, __shfl_xor_sync(0xffffffffu, rmax1, 1));
            rmax1 = fmaxf(rmax1, __shfl_xor_sync(0xffffffffu, rmax1, 2));

            float mn0 = fmaxf(m_[0], rmax0), mn1 = fmaxf(m_[1], rmax1);
            float corr0 = __expf(m_[0] - mn0), corr1 = __expf(m_[1] - mn1);
            float sum0 = 0.0f, sum1 = 0.0f;
#pragma unroll
            for (int nt = 0; nt < 8; nt++) {
                s[nt][0] = __expf(s[nt][0] - mn0);
                s[nt][1] = __expf(s[nt][1] - mn0);
                s[nt][2] = __expf(s[nt][2] - mn1);
                s[nt][3] = __expf(s[nt][3] - mn1);
                sum0 += s[nt][0] + s[nt][1];
                sum1 += s[nt][2] + s[nt][3];
            }
            sum0 += __shfl_xor_sync(0xffffffffu, sum0, 1);
            sum0 += __shfl_xor_sync(0xffffffffu, sum0, 2);
            sum1 += __shfl_xor_sync(0xffffffffu, sum1, 1);
            sum1 += __shfl_xor_sync(0xffffffffu, sum1, 2);
            l_[0] = l_[0] * corr0 + sum0;
            l_[1] = l_[1] * corr1 + sum1;
            m_[0] = mn0;
            m_[1] = mn1;
#pragma unroll
            for (int nt = 0; nt < 8; nt++) {
                o[nt][0] *= corr0;
                o[nt][1] *= corr0;
                o[nt][2] *= corr1;
                o[nt][3] *= corr1;
            }

            // O += P V  (P hi/lo compensated, V rounded; V frags via ldmatrix.trans)
#pragma unroll
            for (int ks = 0; ks < 4; ks++) {
                uint32_t ph[4], pl[4];
                split2(s[2 * ks][0],     s[2 * ks][1],     ph[0], pl[0]);
                split2(s[2 * ks][2],     s[2 * ks][3],     ph[1], pl[1]);
                split2(s[2 * ks + 1][0], s[2 * ks + 1][1], ph[2], pl[2]);
                split2(s[2 * ks + 1][2], s[2 * ks + 1][3], ph[3], pl[3]);
#pragma unroll
                for (int p = 0; p < 4; p++) {
                    uint32_t vh[4];
                    uint32_t vaddr = sbase + (se + A_VH +
                        (16 * ks + (sub & 1) * 8 + rrow) * SROW + 16 * p + (sub >> 1) * 8) * 2;
                    LDSM4T(vh, vaddr);
                    mma_f16(o[2 * p], ph, vh);
                    mma_f16(o[2 * p], pl, vh);
                    mma_f16(o[2 * p + 1], ph, vh + 2);
                    mma_f16(o[2 * p + 1], pl, vh + 2);
                }
            }
        }
    }

    // normalize + write O (hi/lo) in (T, C) layout
    float inv0 = 1.0f / l_[0], inv1 = 1.0f / l_[1];
#pragma unroll
    for (int nd = 0; nd < 8; nd++) {
        int col = h * HEAD_D + 8 * nd + 2 * t;
        uint32_t h0, l0, h1, l1;
        split2(o[nd][0] * inv0, o[nd][1] * inv0, h0, l0);
        split2(o[nd][2] * inv1, o[nd][3] * inv1, h1, l1);
        size_t o1 = (size_t)r0 * C_DIM + col;
        size_t o2 = (size_t)(r0 + 8) * C_DIM + col;
        *(uint32_t*)&g_Oh[o1] = h0; *(uint32_t*)&g_Ol[o1] = l0;
        *(uint32_t*)&g_Oh[o2] = h1; *(uint32_t*)&g_Ol[o2] = l1;
    }
}

// ----------------------------------------------------------------------------
extern "C" void kernel_launch(void* const* d_in, const int* in_sizes, int n_in,
                              void* d_out, int out_size)
{
    const float* x  = (const float*)d_in[0];
    const float* wq = (const float*)d_in[1];
    const float* wk = (const float*)d_in[2];
    const float* wv = (const float*)d_in[3];
    const float* wo = (const float*)d_in[4];
    float* out = (float*)d_out;

    cudaFuncSetAttribute(gemm_hf<0>, cudaFuncAttributeMaxDynamicSharedMemorySize, GEMM_SMEM);
    cudaFuncSetAttribute(gemm_hf<1>, cudaFuncAttributeMaxDynamicSharedMemorySize, GEMM_SMEM);
    cudaFuncSetAttribute(attn_hf, cudaFuncAttributeMaxDynamicSharedMemorySize, ATTN_SMEM);

    // 0) one-time conversion
    convert_kernel<<<(NCONV + 255) / 256, 256>>>(x, wq, wk, wv, wo);

    // 1) QKV projections
    gemm_hf<0><<<dim3(C_DIM / 64, T_SEQ / 128, 3), 256, GEMM_SMEM>>>(nullptr);

    // 2) flash attention
    attn_hf<<<dim3(T_SEQ / 128, N_HEAD), 256, ATTN_SMEM>>>();

    // 3) output projection -> fp32
    gemm_hf<1><<<dim3(C_DIM / 64, T_SEQ / 128, 1), 256, GEMM_SMEM>>>(out);
}

// round 8
// speedup vs baseline: 5.7377x; 1.2548x over previous
#include <cuda_runtime.h>
#include <cuda_fp16.h>
#include <cstdint>
#include <math.h>

#define T_SEQ 4096
#define C_DIM 768
#define N_HEAD 12
#define HEAD_D 64
#define NW (C_DIM * C_DIM)
#define SROW 72   // smem row stride in halves (144B: conflict-free ldmatrix + cp.async)

// Q pre-scale: 1/sqrt(64) * log2(e)  (puts S directly in log2 domain)
#define QSC 0.1803368801111204f

// ----------------------------------------------------------------------------
// Device-global scratch (no allocation allowed)
// ----------------------------------------------------------------------------
__device__ __half g_Xh[T_SEQ * C_DIM], g_Xl[T_SEQ * C_DIM];
__device__ __half g_Wh[4 * NW];
__device__ __half g_Qh[N_HEAD * T_SEQ * HEAD_D], g_Ql[N_HEAD * T_SEQ * HEAD_D];
__device__ __half g_Kh[N_HEAD * T_SEQ * HEAD_D];
__device__ __half g_Vh[N_HEAD * T_SEQ * HEAD_D];
__device__ __half g_Oh[T_SEQ * C_DIM], g_Ol[T_SEQ * C_DIM];

// ----------------------------------------------------------------------------
// PTX helpers (baseline ISA only — plain sm_103 target)
// ----------------------------------------------------------------------------
__device__ __forceinline__ uint32_t smem_u32(const void* p) {
    uint32_t a;
    asm("{ .reg .u64 t; cvta.to.shared.u64 t, %1; cvt.u32.u64 %0, t; }"
        : "=r"(a) : "l"(p));
    return a;
}

__device__ __forceinline__ void mma_f16(float* c, const uint32_t* a, const uint32_t* b) {
    asm volatile(
        "mma.sync.aligned.m16n8k16.row.col.f32.f16.f16.f32 "
        "{%0,%1,%2,%3}, {%4,%5,%6,%7}, {%8,%9}, {%0,%1,%2,%3};"
        : "+f"(c[0]), "+f"(c[1]), "+f"(c[2]), "+f"(c[3])
        : "r"(a[0]), "r"(a[1]), "r"(a[2]), "r"(a[3]), "r"(b[0]), "r"(b[1]));
}

#define LDSM4(r, a) \
    asm volatile("ldmatrix.sync.aligned.m8n8.x4.shared.b16 {%0,%1,%2,%3}, [%4];" \
        : "=r"((r)[0]), "=r"((r)[1]), "=r"((r)[2]), "=r"((r)[3]) : "r"(a))
#define LDSM4T(r, a) \
    asm volatile("ldmatrix.sync.aligned.m8n8.x4.trans.shared.b16 {%0,%1,%2,%3}, [%4];" \
        : "=r"((r)[0]), "=r"((r)[1]), "=r"((r)[2]), "=r"((r)[3]) : "r"(a))

#define CP16(dst, src) \
    asm volatile("cp.async.cg.shared.global [%0], [%1], 16;" :: "r"(dst), "l"(src))
#define CP_COMMIT() asm volatile("cp.async.commit_group;" ::: "memory")
#define CP_WAIT0() asm volatile("cp.async.wait_group 0;" ::: "memory")
#define CP_WAIT1() asm volatile("cp.async.wait_group 1;" ::: "memory")

__device__ __forceinline__ uint32_t pack_h2(float x, float y) {
    __half2 h = __float22half2_rn(make_float2(x, y));
    return *reinterpret_cast<uint32_t*>(&h);
}

// fp16 hi + residual-lo split of a float pair
__device__ __forceinline__ void split2(float x, float y, uint32_t& hi, uint32_t& lo) {
    __half2 h2 = __float22half2_rn(make_float2(x, y));
    float2 hf = __half22float2(h2);
    __half2 l2 = __float22half2_rn(make_float2(x - hf.x, y - hf.y));
    hi = *reinterpret_cast<uint32_t*>(&h2);
    lo = *reinterpret_cast<uint32_t*>(&l2);
}

// packed 2^x for a float pair -> fp16x2 (elem0 in low half)
__device__ __forceinline__ uint32_t h2exp2(float lo_e, float hi_e) {
    uint32_t d;
    asm("cvt.rn.f16x2.f32 %0, %1, %2;" : "=r"(d) : "f"(hi_e), "f"(lo_e));
    asm("ex2.approx.f16x2 %0, %0;" : "+r"(d));
    return d;
}

// ----------------------------------------------------------------------------
// Pre-convert: x -> fp16 hi/lo ; weights -> fp16 hi only
// ----------------------------------------------------------------------------
#define NX4 (T_SEQ * C_DIM / 4)
#define NW4 (NW / 4)
#define NCONV (NX4 + 4 * NW4)

__global__ __launch_bounds__(256) void convert_kernel(
    const float* __restrict__ x,  const float* __restrict__ wq,
    const float* __restrict__ wk, const float* __restrict__ wv,
    const float* __restrict__ wo)
{
    int i = blockIdx.x * 256 + threadIdx.x;
    if (i >= NCONV) return;
    if (i < NX4) {
        float4 v = ((const float4*)x)[i];
        uint32_t h0, l0, h1, l1;
        split2(v.x, v.y, h0, l0);
        split2(v.z, v.w, h1, l1);
        ((uint2*)g_Xh)[i] = make_uint2(h0, h1);
        ((uint2*)g_Xl)[i] = make_uint2(l0, l1);
    } else {
        int wi = (i - NX4) / NW4;
        size_t off = (i - NX4) % NW4;
        const float* src = (wi == 0) ? wq : (wi == 1) ? wk : (wi == 2) ? wv : wo;
        float4 v = ((const float4*)src)[off];
        ((uint2*)(g_Wh + (size_t)wi * NW))[off] =
            make_uint2(pack_h2(v.x, v.y), pack_h2(v.z, v.w));
    }
}

// ----------------------------------------------------------------------------
// GEMM C[M,N] = A @ W^T; A fp16 hi/lo (2-MMA compensation), W fp16.
// CTA 128x64, 8 warps (warp: 16 rows), K-chunk 64, 2-stage cp.async.
// MODE 0: A=g_X*, W=g_Wh[z] -> Q hi/lo (scaled by QSC) / K hi / V hi
// MODE 1: A=g_O*, W=g_Wh[3] -> fp32 out
// ----------------------------------------------------------------------------
#define G_AH 0
#define G_AL 9216
#define G_BH 18432
#define G_STG 23040
static constexpr int GEMM_SMEM = 2 * G_STG * 2;  // 92160 B

template <int MODE>
__global__ __launch_bounds__(256) void gemm_hf(float* __restrict__ outp)
{
    extern __shared__ __half sb[];
    const uint32_t sbase = smem_u32(sb);
    const int tid = threadIdx.x;
    const int w = tid >> 5, lane = tid & 31;
    const int g = lane >> 2, t = lane & 3;
    const int sub = lane >> 3, rrow = lane & 7;
    const int m0 = blockIdx.y * 128, n0 = blockIdx.x * 64;
    const int z = (MODE == 0) ? blockIdx.z : 3;

    const __half* Ah = (MODE == 0) ? g_Xh : g_Oh;
    const __half* Al = (MODE == 0) ? g_Xl : g_Ol;
    const __half* Bh = g_Wh + (size_t)z * NW;

    float c[8][4];
#pragma unroll
    for (int i = 0; i < 8; i++)
#pragma unroll
        for (int j = 0; j < 4; j++) c[i][j] = 0.0f;

    auto load_stage = [&](int s, int ch) {
        const int k0 = ch * 64;
        const uint32_t se = s * G_STG;
#pragma unroll
        for (int p = 0; p < 4; p++) {
            int slot = tid + p * 256;
            int r = slot >> 3, cc = (slot & 7) * 8;
            CP16(sbase + (se + G_AH + r * SROW + cc) * 2,
                 &Ah[(size_t)(m0 + r) * C_DIM + k0 + cc]);
            CP16(sbase + (se + G_AL + r * SROW + cc) * 2,
                 &Al[(size_t)(m0 + r) * C_DIM + k0 + cc]);
        }
#pragma unroll
        for (int p = 0; p < 2; p++) {
            int slot = tid + p * 256;
            int r = slot >> 3, cc = (slot & 7) * 8;
            CP16(sbase + (se + G_BH + r * SROW + cc) * 2,
                 &Bh[(size_t)(n0 + r) * C_DIM + k0 + cc]);
        }
        CP_COMMIT();
    };

    load_stage(0, 0);
    const int NCH = C_DIM / 64;
    for (int ch = 0; ch < NCH; ch++) {
        bool more = (ch + 1 < NCH);
        if (more) load_stage((ch + 1) & 1, ch + 1);
        if (more) CP_WAIT1(); else CP_WAIT0();
        __syncthreads();
        const uint32_t se = (ch & 1) * G_STG;
#pragma unroll
        for (int ks = 0; ks < 4; ks++) {
            uint32_t ah[4], al[4];
            uint32_t aaddr = sbase + (se + G_AH +
                (16 * w + (sub & 1) * 8 + rrow) * SROW + 16 * ks + (sub >> 1) * 8) * 2;
            LDSM4(ah, aaddr);
            LDSM4(al, aaddr + (G_AL - G_AH) * 2);
#pragma unroll
            for (int p = 0; p < 4; p++) {
                uint32_t bh[4];
                uint32_t baddr = sbase + (se + G_BH +
                    (16 * p + (sub >> 1) * 8 + rrow) * SROW + 16 * ks + (sub & 1) * 8) * 2;
                LDSM4(bh, baddr);
                mma_f16(c[2 * p], ah, bh);
                mma_f16(c[2 * p], al, bh);
                mma_f16(c[2 * p + 1], ah, bh + 2);
                mma_f16(c[2 * p + 1], al, bh + 2);
            }
        }
        __syncthreads();
    }

    const int r0 = m0 + 16 * w + g;
    if (MODE == 0) {
        const int head = blockIdx.x;
        if (z == 0) {
#pragma unroll
            for (int nt = 0; nt < 8; nt++) {
                int cb = 8 * nt + 2 * t;
                uint32_t h0, l0, h1, l1;
                split2(c[nt][0] * QSC, c[nt][1] * QSC, h0, l0);
                split2(c[nt][2] * QSC, c[nt][3] * QSC, h1, l1);
                size_t o1 = ((size_t)head * T_SEQ + r0) * HEAD_D + cb;
                size_t o2 = ((size_t)head * T_SEQ + r0 + 8) * HEAD_D + cb;
                *(uint32_t*)&g_Qh[o1] = h0; *(uint32_t*)&g_Ql[o1] = l0;
                *(uint32_t*)&g_Qh[o2] = h1; *(uint32_t*)&g_Ql[o2] = l1;
            }
        } else {
            __half* dh = (z == 1) ? g_Kh : g_Vh;
#pragma unroll
            for (int nt = 0; nt < 8; nt++) {
                int cb = 8 * nt + 2 * t;
                size_t o1 = ((size_t)head * T_SEQ + r0) * HEAD_D + cb;
                size_t o2 = ((size_t)head * T_SEQ + r0 + 8) * HEAD_D + cb;
                *(uint32_t*)&dh[o1] = pack_h2(c[nt][0], c[nt][1]);
                *(uint32_t*)&dh[o2] = pack_h2(c[nt][2], c[nt][3]);
            }
        }
    } else {
#pragma unroll
        for (int nt = 0; nt < 8; nt++) {
            int cb = 8 * nt + 2 * t;
            *(float2*)&outp[(size_t)r0 * C_DIM + n0 + cb] = make_float2(c[nt][0], c[nt][1]);
            *(float2*)&outp[(size_t)(r0 + 8) * C_DIM + n0 + cb] = make_float2(c[nt][2], c[nt][3]);
        }
    }
}

// ----------------------------------------------------------------------------
// Flash attention (causal), log2-domain softmax with fp16x2 ex2.
// S: Q hi/lo x K (2 MMA). P: fp16 direct from ex2. PV: 1 MMA. Row sums: ones-MMA.
// CTA = (head, 128 q rows), 8 warps; 64-key tiles; 3-stage cp.async pipeline.
// ----------------------------------------------------------------------------
#define A_KH 0
#define A_VH 4608
#define A_STG 9216
static constexpr int ATTN_SMEM = 3 * A_STG * 2;  // 55296 B

__global__ __launch_bounds__(256) void attn_hf()
{
    extern __shared__ __half sa[];
    const uint32_t sbase = smem_u32(sa);
    const int h = blockIdx.y;
    const int qi = gridDim.x - 1 - blockIdx.x;   // long CTAs first
    const int q0 = qi * 128;
    const int tid = threadIdx.x;
    const int w = tid >> 5, lane = tid & 31;
    const int g = lane >> 2, t = lane & 3;
    const int sub = lane >> 3, rrow = lane & 7;

    const __half* Qhp = g_Qh + (size_t)h * T_SEQ * HEAD_D;
    const __half* Qlp = g_Ql + (size_t)h * T_SEQ * HEAD_D;
    const __half* Khp = g_Kh + (size_t)h * T_SEQ * HEAD_D;
    const __half* Vhp = g_Vh + (size_t)h * T_SEQ * HEAD_D;

    const int r0 = q0 + 16 * w + g;

    uint32_t qh[4][4], ql[4][4];
#pragma unroll
    for (int ks = 0; ks < 4; ks++) {
#pragma unroll
        for (int rr = 0; rr < 2; rr++) {
            size_t base = (size_t)(r0 + 8 * rr) * HEAD_D + 16 * ks + 2 * t;
            qh[ks][rr]     = *(const uint32_t*)&Qhp[base];
            qh[ks][rr + 2] = *(const uint32_t*)&Qhp[base + 8];
            ql[ks][rr]     = *(const uint32_t*)&Qlp[base];
            ql[ks][rr + 2] = *(const uint32_t*)&Qlp[base + 8];
        }
    }

    float o[8][4];
#pragma unroll
    for (int i = 0; i < 8; i++)
#pragma unroll
        for (int j = 0; j < 4; j++) o[i][j] = 0.0f;
    float m_[2] = {-1e30f, -1e30f};
    float lsum[4] = {0.0f, 0.0f, 0.0f, 0.0f};
    const uint32_t ones2[2] = {0x3C003C00u, 0x3C003C00u};

    auto load_stage = [&](int j) {
        const int k0 = j * 64;
        const uint32_t se = (j % 3) * A_STG;
#pragma unroll
        for (int p = 0; p < 2; p++) {
            int slot = tid + p * 256;
            int r = slot >> 3, cc = (slot & 7) * 8;
            size_t go = (size_t)(k0 + r) * HEAD_D + cc;
            uint32_t so = (se + r * SROW + cc) * 2;
            CP16(sbase + so + A_KH * 2, &Khp[go]);
            CP16(sbase + so + A_VH * 2, &Vhp[go]);
        }
        CP_COMMIT();
    };

    const int njt = 2 * qi + 2;
    load_stage(0);
    load_stage(1);
    for (int j = 0; j < njt; j++) {
        if (j + 1 < njt) CP_WAIT1(); else CP_WAIT0();
        __syncthreads();
        if (j + 2 < njt) load_stage(j + 2);

        const int k0 = j * 64;
        const uint32_t se = (j % 3) * A_STG;
        const bool active = (k0 <= q0 + 16 * w + 15);

        if (active) {
            float s[8][4];
#pragma unroll
            for (int i = 0; i < 8; i++)
#pragma unroll
                for (int e = 0; e < 4; e++) s[i][e] = 0.0f;

            // S (log2 domain) = Q' K^T  (Q hi/lo compensated, K rounded)
#pragma unroll
            for (int ks = 0; ks < 4; ks++) {
#pragma unroll
                for (int p = 0; p < 4; p++) {
                    uint32_t kh[4];
                    uint32_t kaddr = sbase + (se + A_KH +
                        (16 * p + (sub >> 1) * 8 + rrow) * SROW + 16 * ks + (sub & 1) * 8) * 2;
                    LDSM4(kh, kaddr);
                    mma_f16(s[2 * p], qh[ks], kh);
                    mma_f16(s[2 * p], ql[ks], kh);
                    mma_f16(s[2 * p + 1], qh[ks], kh + 2);
                    mma_f16(s[2 * p + 1], ql[ks], kh + 2);
                }
            }

            // causal mask
            if (k0 + 63 > q0 + 16 * w) {
#pragma unroll
                for (int nt = 0; nt < 8; nt++)
#pragma unroll
                    for (int e = 0; e < 4; e++) {
                        int key = k0 + 8 * nt + 2 * t + (e & 1);
                        int row = r0 + 8 * (e >> 1);
                        if (key > row) s[nt][e] = -1e30f;
                    }
            }

            // running max per row (g, g+8)
            float rmax0 = -1e30f, rmax1 = -1e30f;
#pragma unroll
            for (int nt = 0; nt < 8; nt++) {
                rmax0 = fmaxf(rmax0, fmaxf(s[nt][0], s[nt][1]));
                rmax1 = fmaxf(rmax1, fmaxf(s[nt][2], s[nt][3]));
            }
            rmax0 = fmaxf(rmax0, __shfl_xor_sync(0xffffffffu, rmax0, 1));
            rmax0 = fmaxf(rmax0, __shfl_xor_sync(0xffffffffu, rmax0, 2));
            rmax1 = fmaxf(rmax1, __shfl_xor_sync(0xffffffffu, rmax1, 1));
            rmax1 = fmaxf(rmax1, __shfl_xor_sync(0xffffffffu, rmax1, 2));

            float mn0 = fmaxf(m_[0], rmax0), mn1 = fmaxf(m_[1], rmax1);
            float corr0 = exp2f(m_[0] - mn0), corr1 = exp2f(m_[1] - mn1);
            m_[0] = mn0; m_[1] = mn1;

            // P = 2^(S - m), packed fp16x2 fragments directly
            uint32_t ph[4][4];
#pragma unroll
            for (int ks = 0; ks < 4; ks++) {
                ph[ks][0] = h2exp2(s[2 * ks][0] - mn0,     s[2 * ks][1] - mn0);
                ph[ks][1] = h2exp2(s[2 * ks][2] - mn1,     s[2 * ks][3] - mn1);
                ph[ks][2] = h2exp2(s[2 * ks + 1][0] - mn0, s[2 * ks + 1][1] - mn0);
                ph[ks][3] = h2exp2(s[2 * ks + 1][2] - mn1, s[2 * ks + 1][3] - mn1);
            }

            // rescale running state
            lsum[0] *= corr0; lsum[1] *= corr0;
            lsum[2] *= corr1; lsum[3] *= corr1;
#pragma unroll
            for (int nt = 0; nt < 8; nt++) {
                o[nt][0] *= corr0;
                o[nt][1] *= corr0;
                o[nt][2] *= corr1;
                o[nt][3] *= corr1;
            }

            // row sums via ones-MMA (l accumulates in fp32 on tensor pipe)
#pragma unroll
            for (int ks = 0; ks < 4; ks++) mma_f16(lsum, ph[ks], ones2);

            // O += P V  (V frags via ldmatrix.trans)
#pragma unroll
            for (int ks = 0; ks < 4; ks++) {
#pragma unroll
                for (int p = 0; p < 4; p++) {
                    uint32_t vh[4];
                    uint32_t vaddr = sbase + (se + A_VH +
                        (16 * ks + (sub & 1) * 8 + rrow) * SROW + 16 * p + (sub >> 1) * 8) * 2;
                    LDSM4T(vh, vaddr);
                    mma_f16(o[2 * p], ph[ks], vh);
                    mma_f16(o[2 * p + 1], ph[ks], vh + 2);
                }
            }
        }
    }

    // normalize + write O (hi/lo) in (T, C) layout
    float inv0 = 1.0f / lsum[0], inv1 = 1.0f / lsum[2];
#pragma unroll
    for (int nd = 0; nd < 8; nd++) {
        int col = h * HEAD_D + 8 * nd + 2 * t;
        uint32_t h0, l0, h1, l1;
        split2(o[nd][0] * inv0, o[nd][1] * inv0, h0, l0);
        split2(o[nd][2] * inv1, o[nd][3] * inv1, h1, l1);
        size_t o1 = (size_t)r0 * C_DIM + col;
        size_t o2 = (size_t)(r0 + 8) * C_DIM + col;
        *(uint32_t*)&g_Oh[o1] = h0; *(uint32_t*)&g_Ol[o1] = l0;
        *(uint32_t*)&g_Oh[o2] = h1; *(uint32_t*)&g_Ol[o2] = l1;
    }
}

// ----------------------------------------------------------------------------
extern "C" void kernel_launch(void* const* d_in, const int* in_sizes, int n_in,
                              void* d_out, int out_size)
{
    const float* x  = (const float*)d_in[0];
    const float* wq = (const float*)d_in[1];
    const float* wk = (const float*)d_in[2];
    const float* wv = (const float*)d_in[3];
    const float* wo = (const float*)d_in[4];
    float* out = (float*)d_out;

    cudaFuncSetAttribute(gemm_hf<0>, cudaFuncAttributeMaxDynamicSharedMemorySize, GEMM_SMEM);
    cudaFuncSetAttribute(gemm_hf<1>, cudaFuncAttributeMaxDynamicSharedMemorySize, GEMM_SMEM);
    cudaFuncSetAttribute(attn_hf, cudaFuncAttributeMaxDynamicSharedMemorySize, ATTN_SMEM);

    // 0) one-time conversion
    convert_kernel<<<(NCONV + 255) / 256, 256>>>(x, wq, wk, wv, wo);

    // 1) QKV projections
    gemm_hf<0><<<dim3(C_DIM / 64, T_SEQ / 128, 3), 256, GEMM_SMEM>>>(nullptr);

    // 2) flash attention
    attn_hf<<<dim3(T_SEQ / 128, N_HEAD), 256, ATTN_SMEM>>>();

    // 3) output projection -> fp32
    gemm_hf<1><<<dim3(C_DIM / 64, T_SEQ / 128, 1), 256, GEMM_SMEM>>>(out);
}

// round 9
// speedup vs baseline: 6.1758x; 1.0764x over previous
#include <cuda_runtime.h>
#include <cuda_fp16.h>
#include <cstdint>
#include <math.h>

#define T_SEQ 4096
#define C_DIM 768
#define N_HEAD 12
#define HEAD_D 64
#define NW (C_DIM * C_DIM)
#define SROW 72   // smem row stride in halves (144B: conflict-free ldmatrix + cp.async)

// Q pre-scale: 1/sqrt(64) * log2(e)  (puts S directly in log2 domain)
#define QSC 0.1803368801111204f

// ----------------------------------------------------------------------------
// Device-global scratch (no allocation allowed)
// ----------------------------------------------------------------------------
__device__ __half g_Xh[T_SEQ * C_DIM], g_Xl[T_SEQ * C_DIM];
__device__ __half g_Wh[4 * NW];
__device__ __half g_Qh[N_HEAD * T_SEQ * HEAD_D], g_Ql[N_HEAD * T_SEQ * HEAD_D];
__device__ __half g_Kh[N_HEAD * T_SEQ * HEAD_D];
__device__ __half g_Vh[N_HEAD * T_SEQ * HEAD_D];
__device__ __half g_Oh[T_SEQ * C_DIM];

// ----------------------------------------------------------------------------
// PTX helpers (baseline ISA only — plain sm_103 target)
// ----------------------------------------------------------------------------
__device__ __forceinline__ uint32_t smem_u32(const void* p) {
    uint32_t a;
    asm("{ .reg .u64 t; cvta.to.shared.u64 t, %1; cvt.u32.u64 %0, t; }"
        : "=r"(a) : "l"(p));
    return a;
}

__device__ __forceinline__ void mma_f16(float* c, const uint32_t* a, const uint32_t* b) {
    asm volatile(
        "mma.sync.aligned.m16n8k16.row.col.f32.f16.f16.f32 "
        "{%0,%1,%2,%3}, {%4,%5,%6,%7}, {%8,%9}, {%0,%1,%2,%3};"
        : "+f"(c[0]), "+f"(c[1]), "+f"(c[2]), "+f"(c[3])
        : "r"(a[0]), "r"(a[1]), "r"(a[2]), "r"(a[3]), "r"(b[0]), "r"(b[1]));
}

#define LDSM4(r, a) \
    asm volatile("ldmatrix.sync.aligned.m8n8.x4.shared.b16 {%0,%1,%2,%3}, [%4];" \
        : "=r"((r)[0]), "=r"((r)[1]), "=r"((r)[2]), "=r"((r)[3]) : "r"(a))
#define LDSM4T(r, a) \
    asm volatile("ldmatrix.sync.aligned.m8n8.x4.trans.shared.b16 {%0,%1,%2,%3}, [%4];" \
        : "=r"((r)[0]), "=r"((r)[1]), "=r"((r)[2]), "=r"((r)[3]) : "r"(a))

#define CP16(dst, src) \
    asm volatile("cp.async.cg.shared.global [%0], [%1], 16;" :: "r"(dst), "l"(src))
#define CP_COMMIT() asm volatile("cp.async.commit_group;" ::: "memory")
#define CP_WAIT0() asm volatile("cp.async.wait_group 0;" ::: "memory")
#define CP_WAIT1() asm volatile("cp.async.wait_group 1;" ::: "memory")

__device__ __forceinline__ uint32_t pack_h2(float x, float y) {
    __half2 h = __float22half2_rn(make_float2(x, y));
    return *reinterpret_cast<uint32_t*>(&h);
}

// fp16 hi + residual-lo split of a float pair
__device__ __forceinline__ void split2(float x, float y, uint32_t& hi, uint32_t& lo) {
    __half2 h2 = __float22half2_rn(make_float2(x, y));
    float2 hf = __half22float2(h2);
    __half2 l2 = __float22half2_rn(make_float2(x - hf.x, y - hf.y));
    hi = *reinterpret_cast<uint32_t*>(&h2);
    lo = *reinterpret_cast<uint32_t*>(&l2);
}

// packed 2^x for a float pair -> fp16x2 (elem0 in low half)
__device__ __forceinline__ uint32_t h2exp2(float lo_e, float hi_e) {
    uint32_t d;
    asm("cvt.rn.f16x2.f32 %0, %1, %2;" : "=r"(d) : "f"(hi_e), "f"(lo_e));
    asm("ex2.approx.f16x2 %0, %0;" : "+r"(d));
    return d;
}

// ----------------------------------------------------------------------------
// Pre-convert: x -> fp16 hi/lo ; weights -> fp16 hi only
// ----------------------------------------------------------------------------
#define NX4 (T_SEQ * C_DIM / 4)
#define NW4 (NW / 4)
#define NCONV (NX4 + 4 * NW4)

__global__ __launch_bounds__(256) void convert_kernel(
    const float* __restrict__ x,  const float* __restrict__ wq,
    const float* __restrict__ wk, const float* __restrict__ wv,
    const float* __restrict__ wo)
{
    int i = blockIdx.x * 256 + threadIdx.x;
    if (i >= NCONV) return;
    if (i < NX4) {
        float4 v = ((const float4*)x)[i];
        uint32_t h0, l0, h1, l1;
        split2(v.x, v.y, h0, l0);
        split2(v.z, v.w, h1, l1);
        ((uint2*)g_Xh)[i] = make_uint2(h0, h1);
        ((uint2*)g_Xl)[i] = make_uint2(l0, l1);
    } else {
        int wi = (i - NX4) / NW4;
        size_t off = (i - NX4) % NW4;
        const float* src = (wi == 0) ? wq : (wi == 1) ? wk : (wi == 2) ? wv : wo;
        float4 v = ((const float4*)src)[off];
        ((uint2*)(g_Wh + (size_t)wi * NW))[off] =
            make_uint2(pack_h2(v.x, v.y), pack_h2(v.z, v.w));
    }
}

// ----------------------------------------------------------------------------
// GEMM C[M,N] = A @ W^T.
// MODE 0: A = X. z==0 (Q): hi/lo 2-MMA compensation, out Q hi/lo scaled QSC.
//         z==1/2 (K/V): single-MMA fp16 (compensation is below storage
//         rounding noise), X_lo neither loaded nor multiplied.
// MODE 1: A = O (fp16 only), single-MMA, fp32 out. Smaller stage -> 4 CTA/SM.
// CTA 128x64, 8 warps (warp: 16 rows), K-chunk 64, 2-stage cp.async.
// ----------------------------------------------------------------------------
template <int MODE>
__global__ __launch_bounds__(256) void gemm_hf(float* __restrict__ outp)
{
    // stage layout (halves): A_hi | [A_lo] | B
    constexpr int S_AL = 9216;                                  // A_lo offset (MODE 0 only)
    constexpr int S_BH = (MODE == 0) ? 18432 : 9216;            // B offset
    constexpr int STG  = (MODE == 0) ? 23040 : 13824;           // stage elems

    extern __shared__ __half sb[];
    const uint32_t sbase = smem_u32(sb);
    const int tid = threadIdx.x;
    const int w = tid >> 5, lane = tid & 31;
    const int g = lane >> 2, t = lane & 3;
    const int sub = lane >> 3, rrow = lane & 7;
    const int m0 = blockIdx.y * 128, n0 = blockIdx.x * 64;
    const int z = (MODE == 0) ? blockIdx.z : 3;
    const bool comp = (MODE == 0) && (z == 0);   // hi/lo compensation active

    const __half* Ah = (MODE == 0) ? g_Xh : g_Oh;
    const __half* Al = g_Xl;
    const __half* Bh = g_Wh + (size_t)z * NW;

    float c[8][4];
#pragma unroll
    for (int i = 0; i < 8; i++)
#pragma unroll
        for (int j = 0; j < 4; j++) c[i][j] = 0.0f;

    auto load_stage = [&](int s, int ch) {
        const int k0 = ch * 64;
        const uint32_t se = s * STG;
#pragma unroll
        for (int p = 0; p < 4; p++) {
            int slot = tid + p * 256;
            int r = slot >> 3, cc = (slot & 7) * 8;
            CP16(sbase + (se + r * SROW + cc) * 2,
                 &Ah[(size_t)(m0 + r) * C_DIM + k0 + cc]);
            if (comp)
                CP16(sbase + (se + S_AL + r * SROW + cc) * 2,
                     &Al[(size_t)(m0 + r) * C_DIM + k0 + cc]);
        }
#pragma unroll
        for (int p = 0; p < 2; p++) {
            int slot = tid + p * 256;
            int r = slot >> 3, cc = (slot & 7) * 8;
            CP16(sbase + (se + S_BH + r * SROW + cc) * 2,
                 &Bh[(size_t)(n0 + r) * C_DIM + k0 + cc]);
        }
        CP_COMMIT();
    };

    load_stage(0, 0);
    const int NCH = C_DIM / 64;
    for (int ch = 0; ch < NCH; ch++) {
        bool more = (ch + 1 < NCH);
        if (more) load_stage((ch + 1) & 1, ch + 1);
        if (more) CP_WAIT1(); else CP_WAIT0();
        __syncthreads();
        const uint32_t se = (ch & 1) * STG;
#pragma unroll
        for (int ks = 0; ks < 4; ks++) {
            uint32_t ah[4], al[4];
            uint32_t aaddr = sbase + (se +
                (16 * w + (sub & 1) * 8 + rrow) * SROW + 16 * ks + (sub >> 1) * 8) * 2;
            LDSM4(ah, aaddr);
            if (comp) LDSM4(al, aaddr + S_AL * 2);
#pragma unroll
            for (int p = 0; p < 4; p++) {
                uint32_t bh[4];
                uint32_t baddr = sbase + (se + S_BH +
                    (16 * p + (sub >> 1) * 8 + rrow) * SROW + 16 * ks + (sub & 1) * 8) * 2;
                LDSM4(bh, baddr);
                mma_f16(c[2 * p], ah, bh);
                mma_f16(c[2 * p + 1], ah, bh + 2);
                if (comp) {
                    mma_f16(c[2 * p], al, bh);
                    mma_f16(c[2 * p + 1], al, bh + 2);
                }
            }
        }
        __syncthreads();
    }

    const int r0 = m0 + 16 * w + g;
    if (MODE == 0) {
        const int head = blockIdx.x;
        if (z == 0) {
#pragma unroll
            for (int nt = 0; nt < 8; nt++) {
                int cb = 8 * nt + 2 * t;
                uint32_t h0, l0, h1, l1;
                split2(c[nt][0] * QSC, c[nt][1] * QSC, h0, l0);
                split2(c[nt][2] * QSC, c[nt][3] * QSC, h1, l1);
                size_t o1 = ((size_t)head * T_SEQ + r0) * HEAD_D + cb;
                size_t o2 = ((size_t)head * T_SEQ + r0 + 8) * HEAD_D + cb;
                *(uint32_t*)&g_Qh[o1] = h0; *(uint32_t*)&g_Ql[o1] = l0;
                *(uint32_t*)&g_Qh[o2] = h1; *(uint32_t*)&g_Ql[o2] = l1;
            }
        } else {
            __half* dh = (z == 1) ? g_Kh : g_Vh;
#pragma unroll
            for (int nt = 0; nt < 8; nt++) {
                int cb = 8 * nt + 2 * t;
                size_t o1 = ((size_t)head * T_SEQ + r0) * HEAD_D + cb;
                size_t o2 = ((size_t)head * T_SEQ + r0 + 8) * HEAD_D + cb;
                *(uint32_t*)&dh[o1] = pack_h2(c[nt][0], c[nt][1]);
                *(uint32_t*)&dh[o2] = pack_h2(c[nt][2], c[nt][3]);
            }
        }
    } else {
#pragma unroll
        for (int nt = 0; nt < 8; nt++) {
            int cb = 8 * nt + 2 * t;
            *(float2*)&outp[(size_t)r0 * C_DIM + n0 + cb] = make_float2(c[nt][0], c[nt][1]);
            *(float2*)&outp[(size_t)(r0 + 8) * C_DIM + n0 + cb] = make_float2(c[nt][2], c[nt][3]);
        }
    }
}

static constexpr int GEMM0_SMEM = 2 * 23040 * 2;  // 92160 B
static constexpr int GEMM1_SMEM = 2 * 13824 * 2;  // 55296 B

// ----------------------------------------------------------------------------
// Flash attention (causal), log2-domain softmax with fp16x2 ex2.
// S: Q hi/lo x K (2 MMA). P: fp16 direct from ex2. PV: 1 MMA. Row sums: ones-MMA.
// CTA = (head, 128 q rows), 8 warps; 64-key tiles; 3-stage cp.async pipeline.
// Output O: fp16 only.
// ----------------------------------------------------------------------------
#define A_KH 0
#define A_VH 4608
#define A_STG 9216
static constexpr int ATTN_SMEM = 3 * A_STG * 2;  // 55296 B

__global__ __launch_bounds__(256) void attn_hf()
{
    extern __shared__ __half sa[];
    const uint32_t sbase = smem_u32(sa);
    const int h = blockIdx.y;
    const int qi = gridDim.x - 1 - blockIdx.x;   // long CTAs first
    const int q0 = qi * 128;
    const int tid = threadIdx.x;
    const int w = tid >> 5, lane = tid & 31;
    const int g = lane >> 2, t = lane & 3;
    const int sub = lane >> 3, rrow = lane & 7;

    const __half* Qhp = g_Qh + (size_t)h * T_SEQ * HEAD_D;
    const __half* Qlp = g_Ql + (size_t)h * T_SEQ * HEAD_D;
    const __half* Khp = g_Kh + (size_t)h * T_SEQ * HEAD_D;
    const __half* Vhp = g_Vh + (size_t)h * T_SEQ * HEAD_D;

    const int r0 = q0 + 16 * w + g;

    uint32_t qh[4][4], ql[4][4];
#pragma unroll
    for (int ks = 0; ks < 4; ks++) {
#pragma unroll
        for (int rr = 0; rr < 2; rr++) {
            size_t base = (size_t)(r0 + 8 * rr) * HEAD_D + 16 * ks + 2 * t;
            qh[ks][rr]     = *(const uint32_t*)&Qhp[base];
            qh[ks][rr + 2] = *(const uint32_t*)&Qhp[base + 8];
            ql[ks][rr]     = *(const uint32_t*)&Qlp[base];
            ql[ks][rr + 2] = *(const uint32_t*)&Qlp[base + 8];
        }
    }

    float o[8][4];
#pragma unroll
    for (int i = 0; i < 8; i++)
#pragma unroll
        for (int j = 0; j < 4; j++) o[i][j] = 0.0f;
    float m_[2] = {-1e30f, -1e30f};
    float lsum[4] = {0.0f, 0.0f, 0.0f, 0.0f};
    const uint32_t ones2[2] = {0x3C003C00u, 0x3C003C00u};

    auto load_stage = [&](int j) {
        const int k0 = j * 64;
        const uint32_t se = (j % 3) * A_STG;
#pragma unroll
        for (int p = 0; p < 2; p++) {
            int slot = tid + p * 256;
            int r = slot >> 3, cc = (slot & 7) * 8;
            size_t go = (size_t)(k0 + r) * HEAD_D + cc;
            uint32_t so = (se + r * SROW + cc) * 2;
            CP16(sbase + so + A_KH * 2, &Khp[go]);
            CP16(sbase + so + A_VH * 2, &Vhp[go]);
        }
        CP_COMMIT();
    };

    const int njt = 2 * qi + 2;
    load_stage(0);
    load_stage(1);
    for (int j = 0; j < njt; j++) {
        if (j + 1 < njt) CP_WAIT1(); else CP_WAIT0();
        __syncthreads();
        if (j + 2 < njt) load_stage(j + 2);

        const int k0 = j * 64;
        const uint32_t se = (j % 3) * A_STG;
        const bool active = (k0 <= q0 + 16 * w + 15);

        if (active) {
            float s[8][4];
#pragma unroll
            for (int i = 0; i < 8; i++)
#pragma unroll
                for (int e = 0; e < 4; e++) s[i][e] = 0.0f;

            // S (log2 domain) = Q' K^T  (Q hi/lo compensated, K rounded)
#pragma unroll
            for (int ks = 0; ks < 4; ks++) {
#pragma unroll
                for (int p = 0; p < 4; p++) {
                    uint32_t kh[4];
                    uint32_t kaddr = sbase + (se + A_KH +
                        (16 * p + (sub >> 1) * 8 + rrow) * SROW + 16 * ks + (sub & 1) * 8) * 2;
                    LDSM4(kh, kaddr);
                    mma_f16(s[2 * p], qh[ks], kh);
                    mma_f16(s[2 * p], ql[ks], kh);
                    mma_f16(s[2 * p + 1], qh[ks], kh + 2);
                    mma_f16(s[2 * p + 1], ql[ks], kh + 2);
                }
            }

            // causal mask
            if (k0 + 63 > q0 + 16 * w) {
#pragma unroll
                for (int nt = 0; nt < 8; nt++)
#pragma unroll
                    for (int e = 0; e < 4; e++) {
                        int key = k0 + 8 * nt + 2 * t + (e & 1);
                        int row = r0 + 8 * (e >> 1);
                        if (key > row) s[nt][e] = -1e30f;
                    }
            }

            // running max per row (g, g+8)
            float rmax0 = -1e30f, rmax1 = -1e30f;
#pragma unroll
            for (int nt = 0; nt < 8; nt++) {
                rmax0 = fmaxf(rmax0, fmaxf(s[nt][0], s[nt][1]));
                rmax1 = fmaxf(rmax1, fmaxf(s[nt][2], s[nt][3]));
            }
            rmax0 = fmaxf(rmax0, __shfl_xor_sync(0xffffffffu, rmax0, 1));
            rmax0 = fmaxf(rmax0, __shfl_xor_sync(0xffffffffu, rmax0, 2));
            rmax1 = fmaxf(rmax1, __shfl_xor_sync(0xffffffffu, rmax1, 1));
            rmax1 = fmaxf(rmax1, __shfl_xor_sync(0xffffffffu, rmax1, 2));

            float mn0 = fmaxf(m_[0], rmax0), mn1 = fmaxf(m_[1], rmax1);
            float corr0 = exp2f(m_[0] - mn0), corr1 = exp2f(m_[1] - mn1);
            m_[0] = mn0; m_[1] = mn1;

            // P = 2^(S - m), packed fp16x2 fragments directly
            uint32_t ph[4][4];
#pragma unroll
            for (int ks = 0; ks < 4; ks++) {
                ph[ks][0] = h2exp2(s[2 * ks][0] - mn0,     s[2 * ks][1] - mn0);
                ph[ks][1] = h2exp2(s[2 * ks][2] - mn1,     s[2 * ks][3] - mn1);
                ph[ks][2] = h2exp2(s[2 * ks + 1][0] - mn0, s[2 * ks + 1][1] - mn0);
                ph[ks][3] = h2exp2(s[2 * ks + 1][2] - mn1, s[2 * ks + 1][3] - mn1);
            }

            // rescale running state
            lsum[0] *= corr0; lsum[1] *= corr0;
            lsum[2] *= corr1; lsum[3] *= corr1;
#pragma unroll
            for (int nt = 0; nt < 8; nt++) {
                o[nt][0] *= corr0;
                o[nt][1] *= corr0;
                o[nt][2] *= corr1;
                o[nt][3] *= corr1;
            }

            // row sums via ones-MMA (l accumulates in fp32 on tensor pipe)
#pragma unroll
            for (int ks = 0; ks < 4; ks++) mma_f16(lsum, ph[ks], ones2);

            // O += P V  (V frags via ldmatrix.trans)
#pragma unroll
            for (int ks = 0; ks < 4; ks++) {
#pragma unroll
                for (int p = 0; p < 4; p++) {
                    uint32_t vh[4];
                    uint32_t vaddr = sbase + (se + A_VH +
                        (16 * ks + (sub & 1) * 8 + rrow) * SROW + 16 * p + (sub >> 1) * 8) * 2;
                    LDSM4T(vh, vaddr);
                    mma_f16(o[2 * p], ph[ks], vh);
                    mma_f16(o[2 * p + 1], ph[ks], vh + 2);
                }
            }
        }
    }

    // normalize + write O (fp16) in (T, C) layout
    float inv0 = 1.0f / lsum[0], inv1 = 1.0f / lsum[2];
#pragma unroll
    for (int nd = 0; nd < 8; nd++) {
        int col = h * HEAD_D + 8 * nd + 2 * t;
        *(uint32_t*)&g_Oh[(size_t)r0 * C_DIM + col] =
            pack_h2(o[nd][0] * inv0, o[nd][1] * inv0);
        *(uint32_t*)&g_Oh[(size_t)(r0 + 8) * C_DIM + col] =
            pack_h2(o[nd][2] * inv1, o[nd][3] * inv1);
    }
}

// ----------------------------------------------------------------------------
extern "C" void kernel_launch(void* const* d_in, const int* in_sizes, int n_in,
                              void* d_out, int out_size)
{
    const float* x  = (const float*)d_in[0];
    const float* wq = (const float*)d_in[1];
    const float* wk = (const float*)d_in[2];
    const float* wv = (const float*)d_in[3];
    const float* wo = (const float*)d_in[4];
    float* out = (float*)d_out;

    cudaFuncSetAttribute(gemm_hf<0>, cudaFuncAttributeMaxDynamicSharedMemorySize, GEMM0_SMEM);
    cudaFuncSetAttribute(gemm_hf<1>, cudaFuncAttributeMaxDynamicSharedMemorySize, GEMM1_SMEM);
    cudaFuncSetAttribute(attn_hf, cudaFuncAttributeMaxDynamicSharedMemorySize, ATTN_SMEM);

    // 0) one-time conversion
    convert_kernel<<<(NCONV + 255) / 256, 256>>>(x, wq, wk, wv, wo);

    // 1) QKV projections (Q compensated, K/V single-MMA)
    gemm_hf<0><<<dim3(C_DIM / 64, T_SEQ / 128, 3), 256, GEMM0_SMEM>>>(nullptr);

    // 2) flash attention
    attn_hf<<<dim3(T_SEQ / 128, N_HEAD), 256, ATTN_SMEM>>>();

    // 3) output projection -> fp32
    gemm_hf<1><<<dim3(C_DIM / 64, T_SEQ / 128, 1), 256, GEMM1_SMEM>>>(out);
}

// round 10
// speedup vs baseline: 6.5154x; 1.0550x over previous
#include <cuda_runtime.h>
#include <cuda_fp16.h>
#include <cstdint>
#include <math.h>

#define T_SEQ 4096
#define C_DIM 768
#define N_HEAD 12
#define HEAD_D 64
#define NW (C_DIM * C_DIM)
#define SROW 72   // smem row stride in halves (144B: conflict-free ldmatrix + cp.async)

// Q pre-scale: 1/sqrt(64) * log2(e)  (puts S directly in log2 domain)
#define QSC 0.1803368801111204f

// ----------------------------------------------------------------------------
// Device-global scratch (no allocation allowed)
// ----------------------------------------------------------------------------
__device__ __half g_Xh[T_SEQ * C_DIM], g_Xl[T_SEQ * C_DIM];
__device__ __half g_Wh[4 * NW];
__device__ __half g_Qh[N_HEAD * T_SEQ * HEAD_D], g_Ql[N_HEAD * T_SEQ * HEAD_D];
__device__ __half g_Kh[N_HEAD * T_SEQ * HEAD_D];
__device__ __half g_Vh[N_HEAD * T_SEQ * HEAD_D];
__device__ __half g_Oh[T_SEQ * C_DIM];

// ----------------------------------------------------------------------------
// PTX helpers (baseline ISA only — plain sm_103 target)
// ----------------------------------------------------------------------------
__device__ __forceinline__ uint32_t smem_u32(const void* p) {
    uint32_t a;
    asm("{ .reg .u64 t; cvta.to.shared.u64 t, %1; cvt.u32.u64 %0, t; }"
        : "=r"(a) : "l"(p));
    return a;
}

__device__ __forceinline__ void mma_f16(float* c, const uint32_t* a, const uint32_t* b) {
    asm volatile(
        "mma.sync.aligned.m16n8k16.row.col.f32.f16.f16.f32 "
        "{%0,%1,%2,%3}, {%4,%5,%6,%7}, {%8,%9}, {%0,%1,%2,%3};"
        : "+f"(c[0]), "+f"(c[1]), "+f"(c[2]), "+f"(c[3])
        : "r"(a[0]), "r"(a[1]), "r"(a[2]), "r"(a[3]), "r"(b[0]), "r"(b[1]));
}

#define LDSM4(r, a) \
    asm volatile("ldmatrix.sync.aligned.m8n8.x4.shared.b16 {%0,%1,%2,%3}, [%4];" \
        : "=r"((r)[0]), "=r"((r)[1]), "=r"((r)[2]), "=r"((r)[3]) : "r"(a))
#define LDSM4T(r, a) \
    asm volatile("ldmatrix.sync.aligned.m8n8.x4.trans.shared.b16 {%0,%1,%2,%3}, [%4];" \
        : "=r"((r)[0]), "=r"((r)[1]), "=r"((r)[2]), "=r"((r)[3]) : "r"(a))

#define CP16(dst, src) \
    asm volatile("cp.async.cg.shared.global [%0], [%1], 16;" :: "r"(dst), "l"(src))
#define CP_COMMIT() asm volatile("cp.async.commit_group;" ::: "memory")
#define CP_WAIT0() asm volatile("cp.async.wait_group 0;" ::: "memory")
#define CP_WAIT1() asm volatile("cp.async.wait_group 1;" ::: "memory")

__device__ __forceinline__ uint32_t pack_h2(float x, float y) {
    __half2 h = __float22half2_rn(make_float2(x, y));
    return *reinterpret_cast<uint32_t*>(&h);
}

// fp16 hi + residual-lo split of a float pair
__device__ __forceinline__ void split2(float x, float y, uint32_t& hi, uint32_t& lo) {
    __half2 h2 = __float22half2_rn(make_float2(x, y));
    float2 hf = __half22float2(h2);
    __half2 l2 = __float22half2_rn(make_float2(x - hf.x, y - hf.y));
    hi = *reinterpret_cast<uint32_t*>(&h2);
    lo = *reinterpret_cast<uint32_t*>(&l2);
}

// packed 2^x for a float pair -> fp16x2 (elem0 in low half)
__device__ __forceinline__ uint32_t h2exp2(float lo_e, float hi_e) {
    uint32_t d;
    asm("cvt.rn.f16x2.f32 %0, %1, %2;" : "=r"(d) : "f"(hi_e), "f"(lo_e));
    asm("ex2.approx.f16x2 %0, %0;" : "+r"(d));
    return d;
}

// ----------------------------------------------------------------------------
// Pre-convert: x -> fp16 hi/lo ; weights -> fp16 hi only
// ----------------------------------------------------------------------------
#define NX4 (T_SEQ * C_DIM / 4)
#define NW4 (NW / 4)
#define NCONV (NX4 + 4 * NW4)

__global__ __launch_bounds__(256) void convert_kernel(
    const float* __restrict__ x,  const float* __restrict__ wq,
    const float* __restrict__ wk, const float* __restrict__ wv,
    const float* __restrict__ wo)
{
    int i = blockIdx.x * 256 + threadIdx.x;
    if (i >= NCONV) return;
    if (i < NX4) {
        float4 v = ((const float4*)x)[i];
        uint32_t h0, l0, h1, l1;
        split2(v.x, v.y, h0, l0);
        split2(v.z, v.w, h1, l1);
        ((uint2*)g_Xh)[i] = make_uint2(h0, h1);
        ((uint2*)g_Xl)[i] = make_uint2(l0, l1);
    } else {
        int wi = (i - NX4) / NW4;
        size_t off = (i - NX4) % NW4;
        const float* src = (wi == 0) ? wq : (wi == 1) ? wk : (wi == 2) ? wv : wo;
        float4 v = ((const float4*)src)[off];
        ((uint2*)(g_Wh + (size_t)wi * NW))[off] =
            make_uint2(pack_h2(v.x, v.y), pack_h2(v.z, v.w));
    }
}

// ----------------------------------------------------------------------------
// GEMM C[M,N] = A @ W^T.  CTA tile 128x128, 8 warps (warp: 16 rows x 128 cols).
// K-chunk 64, 2-stage cp.async.
// MODE 0: A = X. z==0 (Q): hi/lo 2-MMA compensation -> Q hi/lo scaled QSC.
//         z==1/2 (K/V): single-MMA fp16. N-tile spans 2 heads.
// MODE 1: A = O (fp16 only), single-MMA, fp32 out.
// Stage layout (halves): A_hi[0..9216) | B[9216..18432) | A_lo[18432..27648)
// ----------------------------------------------------------------------------
template <int MODE>
__global__ __launch_bounds__(256) void gemm_hf(float* __restrict__ outp)
{
    constexpr int S_B  = 9216;
    constexpr int S_AL = 18432;
    constexpr int STG  = (MODE == 0) ? 27648 : 18432;

    extern __shared__ __half sb[];
    const uint32_t sbase = smem_u32(sb);
    const int tid = threadIdx.x;
    const int w = tid >> 5, lane = tid & 31;
    const int g = lane >> 2, t = lane & 3;
    const int sub = lane >> 3, rrow = lane & 7;
    const int m0 = blockIdx.y * 128, n0 = blockIdx.x * 128;
    const int z = (MODE == 0) ? blockIdx.z : 3;
    const bool comp = (MODE == 0) && (z == 0);   // hi/lo compensation active

    const __half* Ah = (MODE == 0) ? g_Xh : g_Oh;
    const __half* Al = g_Xl;
    const __half* Bh = g_Wh + (size_t)z * NW;

    float c[16][4];
#pragma unroll
    for (int i = 0; i < 16; i++)
#pragma unroll
        for (int j = 0; j < 4; j++) c[i][j] = 0.0f;

    auto load_stage = [&](int s, int ch) {
        const int k0 = ch * 64;
        const uint32_t se = s * STG;
#pragma unroll
        for (int p = 0; p < 4; p++) {
            int slot = tid + p * 256;
            int r = slot >> 3, cc = (slot & 7) * 8;
            CP16(sbase + (se + r * SROW + cc) * 2,
                 &Ah[(size_t)(m0 + r) * C_DIM + k0 + cc]);
            CP16(sbase + (se + S_B + r * SROW + cc) * 2,
                 &Bh[(size_t)(n0 + r) * C_DIM + k0 + cc]);
            if (comp)
                CP16(sbase + (se + S_AL + r * SROW + cc) * 2,
                     &Al[(size_t)(m0 + r) * C_DIM + k0 + cc]);
        }
        CP_COMMIT();
    };

    load_stage(0, 0);
    const int NCH = C_DIM / 64;
    for (int ch = 0; ch < NCH; ch++) {
        bool more = (ch + 1 < NCH);
        if (more) load_stage((ch + 1) & 1, ch + 1);
        if (more) CP_WAIT1(); else CP_WAIT0();
        __syncthreads();
        const uint32_t se = (ch & 1) * STG;
#pragma unroll
        for (int ks = 0; ks < 4; ks++) {
            uint32_t ah[4], al[4];
            uint32_t aaddr = sbase + (se +
                (16 * w + (sub & 1) * 8 + rrow) * SROW + 16 * ks + (sub >> 1) * 8) * 2;
            LDSM4(ah, aaddr);
            if (comp) LDSM4(al, aaddr + (S_AL)*2);
#pragma unroll
            for (int p = 0; p < 8; p++) {
                uint32_t bh[4];
                uint32_t baddr = sbase + (se + S_B +
                    (16 * p + (sub >> 1) * 8 + rrow) * SROW + 16 * ks + (sub & 1) * 8) * 2;
                LDSM4(bh, baddr);
                mma_f16(c[2 * p], ah, bh);
                mma_f16(c[2 * p + 1], ah, bh + 2);
                if (comp) {
                    mma_f16(c[2 * p], al, bh);
                    mma_f16(c[2 * p + 1], al, bh + 2);
                }
            }
        }
        __syncthreads();
    }

    const int r0 = m0 + 16 * w + g;
    if (MODE == 0) {
#pragma unroll
        for (int nt = 0; nt < 16; nt++) {
            const int head = n0 / 64 + (nt >> 3);       // N-tile covers 2 heads
            const int cb = 8 * (nt & 7) + 2 * t;        // column within head
            size_t o1 = ((size_t)head * T_SEQ + r0) * HEAD_D + cb;
            size_t o2 = ((size_t)head * T_SEQ + r0 + 8) * HEAD_D + cb;
            if (z == 0) {
                uint32_t h0, l0, h1, l1;
                split2(c[nt][0] * QSC, c[nt][1] * QSC, h0, l0);
                split2(c[nt][2] * QSC, c[nt][3] * QSC, h1, l1);
                *(uint32_t*)&g_Qh[o1] = h0; *(uint32_t*)&g_Ql[o1] = l0;
                *(uint32_t*)&g_Qh[o2] = h1; *(uint32_t*)&g_Ql[o2] = l1;
            } else {
                __half* dh = (z == 1) ? g_Kh : g_Vh;
                *(uint32_t*)&dh[o1] = pack_h2(c[nt][0], c[nt][1]);
                *(uint32_t*)&dh[o2] = pack_h2(c[nt][2], c[nt][3]);
            }
        }
    } else {
#pragma unroll
        for (int nt = 0; nt < 16; nt++) {
            int cb = n0 + 8 * nt + 2 * t;
            *(float2*)&outp[(size_t)r0 * C_DIM + cb] = make_float2(c[nt][0], c[nt][1]);
            *(float2*)&outp[(size_t)(r0 + 8) * C_DIM + cb] = make_float2(c[nt][2], c[nt][3]);
        }
    }
}

static constexpr int GEMM0_SMEM = 2 * 27648 * 2;  // 110592 B
static constexpr int GEMM1_SMEM = 2 * 18432 * 2;  // 73728 B

// ----------------------------------------------------------------------------
// Flash attention (causal), log2-domain softmax with fp16x2 ex2.
// S: Q hi/lo x K (2 MMA). P: fp16 direct from ex2. PV: 1 MMA. Row sums: ones-MMA.
// Warp-voted rescale skip when no row max changes (corr == 1 exactly).
// CTA = (head, 128 q rows), 8 warps; 64-key tiles; 3-stage cp.async pipeline.
// ----------------------------------------------------------------------------
#define A_KH 0
#define A_VH 4608
#define A_STG 9216
static constexpr int ATTN_SMEM = 3 * A_STG * 2;  // 55296 B

__global__ __launch_bounds__(256) void attn_hf()
{
    extern __shared__ __half sa[];
    const uint32_t sbase = smem_u32(sa);
    const int h = blockIdx.y;
    const int qi = gridDim.x - 1 - blockIdx.x;   // long CTAs first
    const int q0 = qi * 128;
    const int tid = threadIdx.x;
    const int w = tid >> 5, lane = tid & 31;
    const int g = lane >> 2, t = lane & 3;
    const int sub = lane >> 3, rrow = lane & 7;

    const __half* Qhp = g_Qh + (size_t)h * T_SEQ * HEAD_D;
    const __half* Qlp = g_Ql + (size_t)h * T_SEQ * HEAD_D;
    const __half* Khp = g_Kh + (size_t)h * T_SEQ * HEAD_D;
    const __half* Vhp = g_Vh + (size_t)h * T_SEQ * HEAD_D;

    const int r0 = q0 + 16 * w + g;

    uint32_t qh[4][4], ql[4][4];
#pragma unroll
    for (int ks = 0; ks < 4; ks++) {
#pragma unroll
        for (int rr = 0; rr < 2; rr++) {
            size_t base = (size_t)(r0 + 8 * rr) * HEAD_D + 16 * ks + 2 * t;
            qh[ks][rr]     = *(const uint32_t*)&Qhp[base];
            qh[ks][rr + 2] = *(const uint32_t*)&Qhp[base + 8];
            ql[ks][rr]     = *(const uint32_t*)&Qlp[base];
            ql[ks][rr + 2] = *(const uint32_t*)&Qlp[base + 8];
        }
    }

    float o[8][4];
#pragma unroll
    for (int i = 0; i < 8; i++)
#pragma unroll
        for (int j = 0; j < 4; j++) o[i][j] = 0.0f;
    float m_[2] = {-1e30f, -1e30f};
    float lsum[4] = {0.0f, 0.0f, 0.0f, 0.0f};
    const uint32_t ones2[2] = {0x3C003C00u, 0x3C003C00u};

    auto load_stage = [&](int j) {
        const int k0 = j * 64;
        const uint32_t se = (j % 3) * A_STG;
#pragma unroll
        for (int p = 0; p < 2; p++) {
            int slot = tid + p * 256;
            int r = slot >> 3, cc = (slot & 7) * 8;
            size_t go = (size_t)(k0 + r) * HEAD_D + cc;
            uint32_t so = (se + r * SROW + cc) * 2;
            CP16(sbase + so + A_KH * 2, &Khp[go]);
            CP16(sbase + so + A_VH * 2, &Vhp[go]);
        }
        CP_COMMIT();
    };

    const int njt = 2 * qi + 2;
    load_stage(0);
    load_stage(1);
    for (int j = 0; j < njt; j++) {
        if (j + 1 < njt) CP_WAIT1(); else CP_WAIT0();
        __syncthreads();
        if (j + 2 < njt) load_stage(j + 2);

        const int k0 = j * 64;
        const uint32_t se = (j % 3) * A_STG;
        const bool active = (k0 <= q0 + 16 * w + 15);

        if (active) {
            float s[8][4];
#pragma unroll
            for (int i = 0; i < 8; i++)
#pragma unroll
                for (int e = 0; e < 4; e++) s[i][e] = 0.0f;

            // S (log2 domain) = Q' K^T  (Q hi/lo compensated, K rounded)
#pragma unroll
            for (int ks = 0; ks < 4; ks++) {
#pragma unroll
                for (int p = 0; p < 4; p++) {
                    uint32_t kh[4];
                    uint32_t kaddr = sbase + (se + A_KH +
                        (16 * p + (sub >> 1) * 8 + rrow) * SROW + 16 * ks + (sub & 1) * 8) * 2;
                    LDSM4(kh, kaddr);
                    mma_f16(s[2 * p], qh[ks], kh);
                    mma_f16(s[2 * p], ql[ks], kh);
                    mma_f16(s[2 * p + 1], qh[ks], kh + 2);
                    mma_f16(s[2 * p + 1], ql[ks], kh + 2);
                }
            }

            // causal mask
            if (k0 + 63 > q0 + 16 * w) {
#pragma unroll
                for (int nt = 0; nt < 8; nt++)
#pragma unroll
                    for (int e = 0; e < 4; e++) {
                        int key = k0 + 8 * nt + 2 * t + (e & 1);
                        int row = r0 + 8 * (e >> 1);
                        if (key > row) s[nt][e] = -1e30f;
                    }
            }

            // running max per row (g, g+8)
            float rmax0 = -1e30f, rmax1 = -1e30f;
#pragma unroll
            for (int nt = 0; nt < 8; nt++) {
                rmax0 = fmaxf(rmax0, fmaxf(s[nt][0], s[nt][1]));
                rmax1 = fmaxf(rmax1, fmaxf(s[nt][2], s[nt][3]));
            }
            rmax0 = fmaxf(rmax0, __shfl_xor_sync(0xffffffffu, rmax0, 1));
            rmax0 = fmaxf(rmax0, __shfl_xor_sync(0xffffffffu, rmax0, 2));
            rmax1 = fmaxf(rmax1, __shfl_xor_sync(0xffffffffu, rmax1, 1));
            rmax1 = fmaxf(rmax1, __shfl_xor_sync(0xffffffffu, rmax1, 2));

            float mn0 = fmaxf(m_[0], rmax0), mn1 = fmaxf(m_[1], rmax1);

            // warp-voted skip: if no row's max moved, corr == 1 exactly
            bool chg = (mn0 > m_[0]) || (mn1 > m_[1]);
            if (__any_sync(0xffffffffu, chg)) {
                float corr0 = exp2f(m_[0] - mn0), corr1 = exp2f(m_[1] - mn1);
                lsum[0] *= corr0; lsum[1] *= corr0;
                lsum[2] *= corr1; lsum[3] *= corr1;
#pragma unroll
                for (int nt = 0; nt < 8; nt++) {
                    o[nt][0] *= corr0;
                    o[nt][1] *= corr0;
                    o[nt][2] *= corr1;
                    o[nt][3] *= corr1;
                }
                m_[0] = mn0; m_[1] = mn1;
            }

            // P = 2^(S - m), packed fp16x2 fragments directly
            uint32_t ph[4][4];
#pragma unroll
            for (int ks = 0; ks < 4; ks++) {
                ph[ks][0] = h2exp2(s[2 * ks][0] - m_[0],     s[2 * ks][1] - m_[0]);
                ph[ks][1] = h2exp2(s[2 * ks][2] - m_[1],     s[2 * ks][3] - m_[1]);
                ph[ks][2] = h2exp2(s[2 * ks + 1][0] - m_[0], s[2 * ks + 1][1] - m_[0]);
                ph[ks][3] = h2exp2(s[2 * ks + 1][2] - m_[1], s[2 * ks + 1][3] - m_[1]);
            }

            // row sums via ones-MMA (l accumulates in fp32 on tensor pipe)
#pragma unroll
            for (int ks = 0; ks < 4; ks++) mma_f16(lsum, ph[ks], ones2);

            // O += P V  (V frags via ldmatrix.trans)
#pragma unroll
            for (int ks = 0; ks < 4; ks++) {
#pragma unroll
                for (int p = 0; p < 4; p++) {
                    uint32_t vh[4];
                    uint32_t vaddr = sbase + (se + A_VH +
                        (16 * ks + (sub & 1) * 8 + rrow) * SROW + 16 * p + (sub >> 1) * 8) * 2;
                    LDSM4T(vh, vaddr);
                    mma_f16(o[2 * p], ph[ks], vh);
                    mma_f16(o[2 * p + 1], ph[ks], vh + 2);
                }
            }
        }
    }

    // normalize + write O (fp16) in (T, C) layout
    float inv0 = 1.0f / lsum[0], inv1 = 1.0f / lsum[2];
#pragma unroll
    for (int nd = 0; nd < 8; nd++) {
        int col = h * HEAD_D + 8 * nd + 2 * t;
        *(uint32_t*)&g_Oh[(size_t)r0 * C_DIM + col] =
            pack_h2(o[nd][0] * inv0, o[nd][1] * inv0);
        *(uint32_t*)&g_Oh[(size_t)(r0 + 8) * C_DIM + col] =
            pack_h2(o[nd][2] * inv1, o[nd][3] * inv1);
    }
}

// ----------------------------------------------------------------------------
extern "C" void kernel_launch(void* const* d_in, const int* in_sizes, int n_in,
                              void* d_out, int out_size)
{
    const float* x  = (const float*)d_in[0];
    const float* wq = (const float*)d_in[1];
    const float* wk = (const float*)d_in[2];
    const float* wv = (const float*)d_in[3];
    const float* wo = (const float*)d_in[4];
    float* out = (float*)d_out;

    cudaFuncSetAttribute(gemm_hf<0>, cudaFuncAttributeMaxDynamicSharedMemorySize, GEMM0_SMEM);
    cudaFuncSetAttribute(gemm_hf<1>, cudaFuncAttributeMaxDynamicSharedMemorySize, GEMM1_SMEM);
    cudaFuncSetAttribute(attn_hf, cudaFuncAttributeMaxDynamicSharedMemorySize, ATTN_SMEM);

    // 0) one-time conversion
    convert_kernel<<<(NCONV + 255) / 256, 256>>>(x, wq, wk, wv, wo);

    // 1) QKV projections (Q compensated, K/V single-MMA), 128x128 tiles
    gemm_hf<0><<<dim3(C_DIM / 128, T_SEQ / 128, 3), 256, GEMM0_SMEM>>>(nullptr);

    // 2) flash attention
    attn_hf<<<dim3(T_SEQ / 128, N_HEAD), 256, ATTN_SMEM>>>();

    // 3) output projection -> fp32, 128x128 tiles
    gemm_hf<1><<<dim3(C_DIM / 128, T_SEQ / 128, 1), 256, GEMM1_SMEM>>>(out);
}

// round 11
// speedup vs baseline: 6.6612x; 1.0224x over previous
#include <cuda_runtime.h>
#include <cuda_fp16.h>
#include <cstdint>
#include <math.h>

#define T_SEQ 4096
#define C_DIM 768
#define N_HEAD 12
#define HEAD_D 64
#define NW (C_DIM * C_DIM)
#define SROW 72   // smem row stride in halves (144B: conflict-free ldmatrix + cp.async)

// Q pre-scale: 1/sqrt(64) * log2(e)  (puts S directly in log2 domain)
#define QSC 0.1803368801111204f

// ----------------------------------------------------------------------------
// Device-global scratch (no allocation allowed)
// ----------------------------------------------------------------------------
__device__ __half g_Xh[T_SEQ * C_DIM], g_Xl[T_SEQ * C_DIM];
__device__ __half g_Wh[4 * NW];
__device__ __half g_Qh[N_HEAD * T_SEQ * HEAD_D], g_Ql[N_HEAD * T_SEQ * HEAD_D];
__device__ __half g_Kh[N_HEAD * T_SEQ * HEAD_D];
__device__ __half g_Vh[N_HEAD * T_SEQ * HEAD_D];
__device__ __half g_Oh[T_SEQ * C_DIM];

// ----------------------------------------------------------------------------
// PTX helpers (baseline ISA only — plain sm_103 target)
// ----------------------------------------------------------------------------
__device__ __forceinline__ uint32_t smem_u32(const void* p) {
    uint32_t a;
    asm("{ .reg .u64 t; cvta.to.shared.u64 t, %1; cvt.u32.u64 %0, t; }"
        : "=r"(a) : "l"(p));
    return a;
}

__device__ __forceinline__ void mma_f16(float* c, const uint32_t* a, const uint32_t* b) {
    asm volatile(
        "mma.sync.aligned.m16n8k16.row.col.f32.f16.f16.f32 "
        "{%0,%1,%2,%3}, {%4,%5,%6,%7}, {%8,%9}, {%0,%1,%2,%3};"
        : "+f"(c[0]), "+f"(c[1]), "+f"(c[2]), "+f"(c[3])
        : "r"(a[0]), "r"(a[1]), "r"(a[2]), "r"(a[3]), "r"(b[0]), "r"(b[1]));
}

#define LDSM4(r, a) \
    asm volatile("ldmatrix.sync.aligned.m8n8.x4.shared.b16 {%0,%1,%2,%3}, [%4];" \
        : "=r"((r)[0]), "=r"((r)[1]), "=r"((r)[2]), "=r"((r)[3]) : "r"(a))
#define LDSM4T(r, a) \
    asm volatile("ldmatrix.sync.aligned.m8n8.x4.trans.shared.b16 {%0,%1,%2,%3}, [%4];" \
        : "=r"((r)[0]), "=r"((r)[1]), "=r"((r)[2]), "=r"((r)[3]) : "r"(a))

#define CP16(dst, src) \
    asm volatile("cp.async.cg.shared.global [%0], [%1], 16;" :: "r"(dst), "l"(src))
#define CP_COMMIT() asm volatile("cp.async.commit_group;" ::: "memory")
#define CP_WAIT0() asm volatile("cp.async.wait_group 0;" ::: "memory")
#define CP_WAIT1() asm volatile("cp.async.wait_group 1;" ::: "memory")

__device__ __forceinline__ uint32_t pack_h2(float x, float y) {
    __half2 h = __float22half2_rn(make_float2(x, y));
    return *reinterpret_cast<uint32_t*>(&h);
}

// fp16 hi + residual-lo split of a float pair
__device__ __forceinline__ void split2(float x, float y, uint32_t& hi, uint32_t& lo) {
    __half2 h2 = __float22half2_rn(make_float2(x, y));
    float2 hf = __half22float2(h2);
    __half2 l2 = __float22half2_rn(make_float2(x - hf.x, y - hf.y));
    hi = *reinterpret_cast<uint32_t*>(&h2);
    lo = *reinterpret_cast<uint32_t*>(&l2);
}

// packed 2^x for a float pair -> fp16x2 (elem0 in low half)
__device__ __forceinline__ uint32_t h2exp2(float lo_e, float hi_e) {
    uint32_t d;
    asm("cvt.rn.f16x2.f32 %0, %1, %2;" : "=r"(d) : "f"(hi_e), "f"(lo_e));
    asm("ex2.approx.f16x2 %0, %0;" : "+r"(d));
    return d;
}

// ----------------------------------------------------------------------------
// Pre-convert: x -> fp16 hi/lo ; weights -> fp16 hi only
// ----------------------------------------------------------------------------
#define NX4 (T_SEQ * C_DIM / 4)
#define NW4 (NW / 4)
#define NCONV (NX4 + 4 * NW4)

__global__ __launch_bounds__(256) void convert_kernel(
    const float* __restrict__ x,  const float* __restrict__ wq,
    const float* __restrict__ wk, const float* __restrict__ wv,
    const float* __restrict__ wo)
{
    int i = blockIdx.x * 256 + threadIdx.x;
    if (i >= NCONV) return;
    if (i < NX4) {
        float4 v = ((const float4*)x)[i];
        uint32_t h0, l0, h1, l1;
        split2(v.x, v.y, h0, l0);
        split2(v.z, v.w, h1, l1);
        ((uint2*)g_Xh)[i] = make_uint2(h0, h1);
        ((uint2*)g_Xl)[i] = make_uint2(l0, l1);
    } else {
        int wi = (i - NX4) / NW4;
        size_t off = (i - NX4) % NW4;
        const float* src = (wi == 0) ? wq : (wi == 1) ? wk : (wi == 2) ? wv : wo;
        float4 v = ((const float4*)src)[off];
        ((uint2*)(g_Wh + (size_t)wi * NW))[off] =
            make_uint2(pack_h2(v.x, v.y), pack_h2(v.z, v.w));
    }
}

// ----------------------------------------------------------------------------
// GEMM C[M,N] = A @ W^T.  8 warps (warp: 16 rows), K-chunk 64, 2-stage cp.async.
// MODE 0: CTA 128x128 (N spans 2 heads). A=X; z=0 (Q): hi/lo 2-MMA comp.
//         z=1/2 (K/V): single-MMA.
// MODE 1: CTA 128x64 (384 CTAs = better wave fit). A=O fp16, single-MMA, fp32 out.
// Stage layout (halves): A_hi | B | [A_lo]
// ----------------------------------------------------------------------------
template <int MODE>
__global__ __launch_bounds__(256) void gemm_hf(float* __restrict__ outp)
{
    constexpr int BN   = (MODE == 0) ? 128 : 64;
    constexpr int S_B  = 9216;                    // after A_hi (128*72)
    constexpr int S_AL = S_B + BN * SROW;         // MODE 0 only
    constexpr int STG  = (MODE == 0) ? (S_AL + 9216) : S_AL;
    constexpr int NT   = BN / 8;                  // c tiles per warp
    constexpr int BP   = BN / 32;                 // B cp.async iterations

    extern __shared__ __half sb[];
    const uint32_t sbase = smem_u32(sb);
    const int tid = threadIdx.x;
    const int w = tid >> 5, lane = tid & 31;
    const int g = lane >> 2, t = lane & 3;
    const int sub = lane >> 3, rrow = lane & 7;
    const int m0 = blockIdx.y * 128, n0 = blockIdx.x * BN;
    const int z = (MODE == 0) ? blockIdx.z : 3;
    const bool comp = (MODE == 0) && (z == 0);   // hi/lo compensation active

    const __half* Ah = (MODE == 0) ? g_Xh : g_Oh;
    const __half* Al = g_Xl;
    const __half* Bh = g_Wh + (size_t)z * NW;

    float c[NT][4];
#pragma unroll
    for (int i = 0; i < NT; i++)
#pragma unroll
        for (int j = 0; j < 4; j++) c[i][j] = 0.0f;

    auto load_stage = [&](int s, int ch) {
        const int k0 = ch * 64;
        const uint32_t se = s * STG;
#pragma unroll
        for (int p = 0; p < 4; p++) {
            int slot = tid + p * 256;
            int r = slot >> 3, cc = (slot & 7) * 8;
            CP16(sbase + (se + r * SROW + cc) * 2,
                 &Ah[(size_t)(m0 + r) * C_DIM + k0 + cc]);
            if (comp)
                CP16(sbase + (se + S_AL + r * SROW + cc) * 2,
                     &Al[(size_t)(m0 + r) * C_DIM + k0 + cc]);
        }
#pragma unroll
        for (int p = 0; p < BP; p++) {
            int slot = tid + p * 256;
            int r = slot >> 3, cc = (slot & 7) * 8;
            CP16(sbase + (se + S_B + r * SROW + cc) * 2,
                 &Bh[(size_t)(n0 + r) * C_DIM + k0 + cc]);
        }
        CP_COMMIT();
    };

    load_stage(0, 0);
    const int NCH = C_DIM / 64;
    for (int ch = 0; ch < NCH; ch++) {
        bool more = (ch + 1 < NCH);
        if (more) load_stage((ch + 1) & 1, ch + 1);
        if (more) CP_WAIT1(); else CP_WAIT0();
        __syncthreads();
        const uint32_t se = (ch & 1) * STG;
#pragma unroll
        for (int ks = 0; ks < 4; ks++) {
            uint32_t ah[4], al[4];
            uint32_t aaddr = sbase + (se +
                (16 * w + (sub & 1) * 8 + rrow) * SROW + 16 * ks + (sub >> 1) * 8) * 2;
            LDSM4(ah, aaddr);
            if (comp) LDSM4(al, aaddr + S_AL * 2);
#pragma unroll
            for (int p = 0; p < NT / 2; p++) {
                uint32_t bh[4];
                uint32_t baddr = sbase + (se + S_B +
                    (16 * p + (sub >> 1) * 8 + rrow) * SROW + 16 * ks + (sub & 1) * 8) * 2;
                LDSM4(bh, baddr);
                mma_f16(c[2 * p], ah, bh);
                mma_f16(c[2 * p + 1], ah, bh + 2);
                if (comp) {
                    mma_f16(c[2 * p], al, bh);
                    mma_f16(c[2 * p + 1], al, bh + 2);
                }
            }
        }
        __syncthreads();
    }

    const int r0 = m0 + 16 * w + g;
    if (MODE == 0) {
#pragma unroll
        for (int nt = 0; nt < NT; nt++) {
            const int head = n0 / 64 + (nt >> 3);       // N-tile covers 2 heads
            const int cb = 8 * (nt & 7) + 2 * t;        // column within head
            size_t o1 = ((size_t)head * T_SEQ + r0) * HEAD_D + cb;
            size_t o2 = ((size_t)head * T_SEQ + r0 + 8) * HEAD_D + cb;
            if (z == 0) {
                uint32_t h0, l0, h1, l1;
                split2(c[nt][0] * QSC, c[nt][1] * QSC, h0, l0);
                split2(c[nt][2] * QSC, c[nt][3] * QSC, h1, l1);
                *(uint32_t*)&g_Qh[o1] = h0; *(uint32_t*)&g_Ql[o1] = l0;
                *(uint32_t*)&g_Qh[o2] = h1; *(uint32_t*)&g_Ql[o2] = l1;
            } else {
                __half* dh = (z == 1) ? g_Kh : g_Vh;
                *(uint32_t*)&dh[o1] = pack_h2(c[nt][0], c[nt][1]);
                *(uint32_t*)&dh[o2] = pack_h2(c[nt][2], c[nt][3]);
            }
        }
    } else {
#pragma unroll
        for (int nt = 0; nt < NT; nt++) {
            int cb = n0 + 8 * nt + 2 * t;
            *(float2*)&outp[(size_t)r0 * C_DIM + cb] = make_float2(c[nt][0], c[nt][1]);
            *(float2*)&outp[(size_t)(r0 + 8) * C_DIM + cb] = make_float2(c[nt][2], c[nt][3]);
        }
    }
}

static constexpr int GEMM0_SMEM = 2 * 27648 * 2;  // 110592 B
static constexpr int GEMM1_SMEM = 2 * 13824 * 2;  // 55296 B

// ----------------------------------------------------------------------------
// Flash attention (causal), log2-domain softmax with fp16x2 ex2.
// CTA = (head, 64 q rows), 4 warps (warp: 16 rows); 128-key tiles (halved
// per-key softmax scaffolding); 3-stage cp.async pipeline.
// S: Q hi/lo x K (2 MMA). P: fp16 direct from ex2. PV: 1 MMA. Row sums: ones-MMA.
// Warp-voted rescale skip when no row max changes.
// ----------------------------------------------------------------------------
#define A_VOFF 9216                      // V offset within stage (128*SROW)
#define A_STG 18432                      // stage elems: 2*128*72
static constexpr int ATTN_SMEM = 3 * A_STG * 2;  // 110592 B

__global__ __launch_bounds__(128) void attn_hf()
{
    extern __shared__ __half sa[];
    const uint32_t sbase = smem_u32(sa);
    const int h = blockIdx.y;
    const int qi = gridDim.x - 1 - blockIdx.x;   // long CTAs first
    const int q0 = qi * 64;
    const int tid = threadIdx.x;
    const int w = tid >> 5, lane = tid & 31;
    const int g = lane >> 2, t = lane & 3;
    const int sub = lane >> 3, rrow = lane & 7;

    const __half* Qhp = g_Qh + (size_t)h * T_SEQ * HEAD_D;
    const __half* Qlp = g_Ql + (size_t)h * T_SEQ * HEAD_D;
    const __half* Khp = g_Kh + (size_t)h * T_SEQ * HEAD_D;
    const __half* Vhp = g_Vh + (size_t)h * T_SEQ * HEAD_D;

    const int r0 = q0 + 16 * w + g;

    uint32_t qh[4][4], ql[4][4];
#pragma unroll
    for (int ks = 0; ks < 4; ks++) {
#pragma unroll
        for (int rr = 0; rr < 2; rr++) {
            size_t base = (size_t)(r0 + 8 * rr) * HEAD_D + 16 * ks + 2 * t;
            qh[ks][rr]     = *(const uint32_t*)&Qhp[base];
            qh[ks][rr + 2] = *(const uint32_t*)&Qhp[base + 8];
            ql[ks][rr]     = *(const uint32_t*)&Qlp[base];
            ql[ks][rr + 2] = *(const uint32_t*)&Qlp[base + 8];
        }
    }

    float o[8][4];
#pragma unroll
    for (int i = 0; i < 8; i++)
#pragma unroll
        for (int j = 0; j < 4; j++) o[i][j] = 0.0f;
    float m_[2] = {-1e30f, -1e30f};
    float lsum[4] = {0.0f, 0.0f, 0.0f, 0.0f};
    const uint32_t ones2[2] = {0x3C003C00u, 0x3C003C00u};

    auto load_stage = [&](int j) {
        const int k0 = j * 128;
        const uint32_t se = (j % 3) * A_STG;
#pragma unroll
        for (int p = 0; p < 8; p++) {
            int slot = tid + p * 128;
            int r = slot >> 3, cc = (slot & 7) * 8;
            size_t go = (size_t)(k0 + r) * HEAD_D + cc;
            uint32_t so = (se + r * SROW + cc) * 2;
            CP16(sbase + so, &Khp[go]);
            CP16(sbase + so + A_VOFF * 2, &Vhp[go]);
        }
        CP_COMMIT();
    };

    const int njt = (64 * (qi + 1) + 127) / 128;
    load_stage(0);
    if (njt > 1) load_stage(1);
    for (int j = 0; j < njt; j++) {
        if (j + 1 < njt) CP_WAIT1(); else CP_WAIT0();
        __syncthreads();
        if (j + 2 < njt) load_stage(j + 2);

        const int k0 = j * 128;
        const uint32_t se = (j % 3) * A_STG;
        const bool active = (k0 <= q0 + 16 * w + 15);

        if (active) {
            float s[16][4];
#pragma unroll
            for (int i = 0; i < 16; i++)
#pragma unroll
                for (int e = 0; e < 4; e++) s[i][e] = 0.0f;

            // S (log2 domain) = Q' K^T  (Q hi/lo compensated, K rounded)
#pragma unroll
            for (int ks = 0; ks < 4; ks++) {
#pragma unroll
                for (int p = 0; p < 8; p++) {
                    uint32_t kh[4];
                    uint32_t kaddr = sbase + (se +
                        (16 * p + (sub >> 1) * 8 + rrow) * SROW + 16 * ks + (sub & 1) * 8) * 2;
                    LDSM4(kh, kaddr);
                    mma_f16(s[2 * p], qh[ks], kh);
                    mma_f16(s[2 * p], ql[ks], kh);
                    mma_f16(s[2 * p + 1], qh[ks], kh + 2);
                    mma_f16(s[2 * p + 1], ql[ks], kh + 2);
                }
            }

            // causal mask
            if (k0 + 127 > q0 + 16 * w) {
#pragma unroll
                for (int nt = 0; nt < 16; nt++)
#pragma unroll
                    for (int e = 0; e < 4; e++) {
                        int key = k0 + 8 * nt + 2 * t + (e & 1);
                        int row = r0 + 8 * (e >> 1);
                        if (key > row) s[nt][e] = -1e30f;
                    }
            }

            // running max per row (g, g+8)
            float rmax0 = -1e30f, rmax1 = -1e30f;
#pragma unroll
            for (int nt = 0; nt < 16; nt++) {
                rmax0 = fmaxf(rmax0, fmaxf(s[nt][0], s[nt][1]));
                rmax1 = fmaxf(rmax1, fmaxf(s[nt][2], s[nt][3]));
            }
            rmax0 = fmaxf(rmax0, __shfl_xor_sync(0xffffffffu, rmax0, 1));
            rmax0 = fmaxf(rmax0, __shfl_xor_sync(0xffffffffu, rmax0, 2));
            rmax1 = fmaxf(rmax1, __shfl_xor_sync(0xffffffffu, rmax1, 1));
            rmax1 = fmaxf(rmax1, __shfl_xor_sync(0xffffffffu, rmax1, 2));

            float mn0 = fmaxf(m_[0], rmax0), mn1 = fmaxf(m_[1], rmax1);

            // warp-voted skip: if no row's max moved, corr == 1 exactly
            bool chg = (mn0 > m_[0]) || (mn1 > m_[1]);
            if (__any_sync(0xffffffffu, chg)) {
                float corr0 = exp2f(m_[0] - mn0), corr1 = exp2f(m_[1] - mn1);
                lsum[0] *= corr0; lsum[1] *= corr0;
                lsum[2] *= corr1; lsum[3] *= corr1;
#pragma unroll
                for (int nt = 0; nt < 8; nt++) {
                    o[nt][0] *= corr0;
                    o[nt][1] *= corr0;
                    o[nt][2] *= corr1;
                    o[nt][3] *= corr1;
                }
                m_[0] = mn0; m_[1] = mn1;
            }

            // P = 2^(S - m), packed fp16x2 fragments directly
            uint32_t ph[8][4];
#pragma unroll
            for (int ks = 0; ks < 8; ks++) {
                ph[ks][0] = h2exp2(s[2 * ks][0] - m_[0],     s[2 * ks][1] - m_[0]);
                ph[ks][1] = h2exp2(s[2 * ks][2] - m_[1],     s[2 * ks][3] - m_[1]);
                ph[ks][2] = h2exp2(s[2 * ks + 1][0] - m_[0], s[2 * ks + 1][1] - m_[0]);
                ph[ks][3] = h2exp2(s[2 * ks + 1][2] - m_[1], s[2 * ks + 1][3] - m_[1]);
            }

            // row sums via ones-MMA (l accumulates in fp32 on tensor pipe)
#pragma unroll
            for (int ks = 0; ks < 8; ks++) mma_f16(lsum, ph[ks], ones2);

            // O += P V  (V frags via ldmatrix.trans)
#pragma unroll
            for (int ks = 0; ks < 8; ks++) {
#pragma unroll
                for (int p = 0; p < 4; p++) {
                    uint32_t vh[4];
                    uint32_t vaddr = sbase + (se + A_VOFF +
                        (16 * ks + (sub & 1) * 8 + rrow) * SROW + 16 * p + (sub >> 1) * 8) * 2;
                    LDSM4T(vh, vaddr);
                    mma_f16(o[2 * p], ph[ks], vh);
                    mma_f16(o[2 * p + 1], ph[ks], vh + 2);
                }
            }
        }
    }

    // normalize + write O (fp16) in (T, C) layout
    float inv0 = 1.0f / lsum[0], inv1 = 1.0f / lsum[2];
#pragma unroll
    for (int nd = 0; nd < 8; nd++) {
        int col = h * HEAD_D + 8 * nd + 2 * t;
        *(uint32_t*)&g_Oh[(size_t)r0 * C_DIM + col] =
            pack_h2(o[nd][0] * inv0, o[nd][1] * inv0);
        *(uint32_t*)&g_Oh[(size_t)(r0 + 8) * C_DIM + col] =
            pack_h2(o[nd][2] * inv1, o[nd][3] * inv1);
    }
}

// ----------------------------------------------------------------------------
extern "C" void kernel_launch(void* const* d_in, const int* in_sizes, int n_in,
                              void* d_out, int out_size)
{
    const float* x  = (const float*)d_in[0];
    const float* wq = (const float*)d_in[1];
    const float* wk = (const float*)d_in[2];
    const float* wv = (const float*)d_in[3];
    const float* wo = (const float*)d_in[4];
    float* out = (float*)d_out;

    cudaFuncSetAttribute(gemm_hf<0>, cudaFuncAttributeMaxDynamicSharedMemorySize, GEMM0_SMEM);
    cudaFuncSetAttribute(gemm_hf<1>, cudaFuncAttributeMaxDynamicSharedMemorySize, GEMM1_SMEM);
    cudaFuncSetAttribute(attn_hf, cudaFuncAttributeMaxDynamicSharedMemorySize, ATTN_SMEM);

    // 0) one-time conversion
    convert_kernel<<<(NCONV + 255) / 256, 256>>>(x, wq, wk, wv, wo);

    // 1) QKV projections (Q compensated, K/V single-MMA), 128x128 tiles
    gemm_hf<0><<<dim3(C_DIM / 128, T_SEQ / 128, 3), 256, GEMM0_SMEM>>>(nullptr);

    // 2) flash attention: 64-row CTAs, 128-key tiles
    attn_hf<<<dim3(T_SEQ / 64, N_HEAD), 128, ATTN_SMEM>>>();

    // 3) output projection -> fp32, 128x64 tiles (wave-fit)
    gemm_hf<1><<<dim3(C_DIM / 64, T_SEQ / 128, 1), 256, GEMM1_SMEM>>>(out);
}

// round 13
// speedup vs baseline: 6.9817x; 1.0481x over previous
#include <cuda_runtime.h>
#include <cuda_fp16.h>
#include <cstdint>
#include <math.h>

#define T_SEQ 4096
#define C_DIM 768
#define N_HEAD 12
#define HEAD_D 64
#define NW (C_DIM * C_DIM)
#define SROW 72   // smem row stride in halves (144B: conflict-free ldmatrix + cp.async)

// Q pre-scale: 1/sqrt(64) * log2(e)  (puts S directly in log2 domain)
#define QSC 0.1803368801111204f

// ----------------------------------------------------------------------------
// Device-global scratch (no allocation allowed)
// ----------------------------------------------------------------------------
__device__ __half g_Xh[T_SEQ * C_DIM], g_Xl[T_SEQ * C_DIM];
__device__ __half g_Wh[4 * NW];
__device__ __half g_Qh[N_HEAD * T_SEQ * HEAD_D], g_Ql[N_HEAD * T_SEQ * HEAD_D];
__device__ __half g_Kh[N_HEAD * T_SEQ * HEAD_D];
__device__ __half g_Vh[N_HEAD * T_SEQ * HEAD_D];
__device__ __half g_Oh[T_SEQ * C_DIM];

// ----------------------------------------------------------------------------
// PTX helpers (baseline ISA only — plain sm_103 target)
// ----------------------------------------------------------------------------
__device__ __forceinline__ uint32_t smem_u32(const void* p) {
    uint32_t a;
    asm("{ .reg .u64 t; cvta.to.shared.u64 t, %1; cvt.u32.u64 %0, t; }"
        : "=r"(a) : "l"(p));
    return a;
}

__device__ __forceinline__ void mma_f16(float* c, const uint32_t* a, const uint32_t* b) {
    asm volatile(
        "mma.sync.aligned.m16n8k16.row.col.f32.f16.f16.f32 "
        "{%0,%1,%2,%3}, {%4,%5,%6,%7}, {%8,%9}, {%0,%1,%2,%3};"
        : "+f"(c[0]), "+f"(c[1]), "+f"(c[2]), "+f"(c[3])
        : "r"(a[0]), "r"(a[1]), "r"(a[2]), "r"(a[3]), "r"(b[0]), "r"(b[1]));
}

#define LDSM4(r, a) \
    asm volatile("ldmatrix.sync.aligned.m8n8.x4.shared.b16 {%0,%1,%2,%3}, [%4];" \
        : "=r"((r)[0]), "=r"((r)[1]), "=r"((r)[2]), "=r"((r)[3]) : "r"(a))
#define LDSM4T(r, a) \
    asm volatile("ldmatrix.sync.aligned.m8n8.x4.trans.shared.b16 {%0,%1,%2,%3}, [%4];" \
        : "=r"((r)[0]), "=r"((r)[1]), "=r"((r)[2]), "=r"((r)[3]) : "r"(a))

#define CP16(dst, src) \
    asm volatile("cp.async.cg.shared.global [%0], [%1], 16;" :: "r"(dst), "l"(src))
#define CP_COMMIT() asm volatile("cp.async.commit_group;" ::: "memory")
#define CP_WAIT0() asm volatile("cp.async.wait_group 0;" ::: "memory")
#define CP_WAIT1() asm volatile("cp.async.wait_group 1;" ::: "memory")

__device__ __forceinline__ uint32_t pack_h2(float x, float y) {
    __half2 h = __float22half2_rn(make_float2(x, y));
    return *reinterpret_cast<uint32_t*>(&h);
}

// fp16 hi + residual-lo split of a float pair
__device__ __forceinline__ void split2(float x, float y, uint32_t& hi, uint32_t& lo) {
    __half2 h2 = __float22half2_rn(make_float2(x, y));
    float2 hf = __half22float2(h2);
    __half2 l2 = __float22half2_rn(make_float2(x - hf.x, y - hf.y));
    hi = *reinterpret_cast<uint32_t*>(&h2);
    lo = *reinterpret_cast<uint32_t*>(&l2);
}

// packed 2^x for a float pair -> fp16x2 (elem0 in low half)
__device__ __forceinline__ uint32_t h2exp2(float lo_e, float hi_e) {
    uint32_t d;
    asm("cvt.rn.f16x2.f32 %0, %1, %2;" : "=r"(d) : "f"(hi_e), "f"(lo_e));
    asm("ex2.approx.f16x2 %0, %0;" : "+r"(d));
    return d;
}

// ----------------------------------------------------------------------------
// Pre-convert: x -> fp16 hi/lo ; weights -> fp16 hi only
// ----------------------------------------------------------------------------
#define NX4 (T_SEQ * C_DIM / 4)
#define NW4 (NW / 4)
#define NCONV (NX4 + 4 * NW4)

__global__ __launch_bounds__(256) void convert_kernel(
    const float* __restrict__ x,  const float* __restrict__ wq,
    const float* __restrict__ wk, const float* __restrict__ wv,
    const float* __restrict__ wo)
{
    int i = blockIdx.x * 256 + threadIdx.x;
    if (i >= NCONV) return;
    if (i < NX4) {
        float4 v = ((const float4*)x)[i];
        uint32_t h0, l0, h1, l1;
        split2(v.x, v.y, h0, l0);
        split2(v.z, v.w, h1, l1);
        ((uint2*)g_Xh)[i] = make_uint2(h0, h1);
        ((uint2*)g_Xl)[i] = make_uint2(l0, l1);
    } else {
        int wi = (i - NX4) / NW4;
        size_t off = (i - NX4) % NW4;
        const float* src = (wi == 0) ? wq : (wi == 1) ? wk : (wi == 2) ? wv : wo;
        float4 v = ((const float4*)src)[off];
        ((uint2*)(g_Wh + (size_t)wi * NW))[off] =
            make_uint2(pack_h2(v.x, v.y), pack_h2(v.z, v.w));
    }
}

// ----------------------------------------------------------------------------
// GEMM C[M,N] = A @ W^T.  8 warps (warp: 16 rows), K-chunk 64, 2-stage cp.async.
// MODE 0: CTA 128x128 (N spans 2 heads). A=X; z=0 (Q): hi/lo 2-MMA comp.
//         z=1/2 (K/V): single-MMA.
// MODE 1: CTA 128x64 (384 CTAs = wave fit). A=O fp16, single-MMA, fp32 out.
// Stage layout (halves): A_hi | B | [A_lo]
// ----------------------------------------------------------------------------
template <int MODE>
__global__ __launch_bounds__(256) void gemm_hf(float* __restrict__ outp)
{
    constexpr int BN   = (MODE == 0) ? 128 : 64;
    constexpr int S_B  = 9216;                    // after A_hi (128*72)
    constexpr int S_AL = S_B + BN * SROW;         // MODE 0 only
    constexpr int STG  = (MODE == 0) ? (S_AL + 9216) : S_AL;
    constexpr int NT   = BN / 8;                  // c tiles per warp
    constexpr int BP   = BN / 32;                 // B cp.async iterations

    extern __shared__ __half sb[];
    const uint32_t sbase = smem_u32(sb);
    const int tid = threadIdx.x;
    const int w = tid >> 5, lane = tid & 31;
    const int g = lane >> 2, t = lane & 3;
    const int sub = lane >> 3, rrow = lane & 7;
    const int m0 = blockIdx.y * 128, n0 = blockIdx.x * BN;
    const int z = (MODE == 0) ? blockIdx.z : 3;
    const bool comp = (MODE == 0) && (z == 0);   // hi/lo compensation active

    const __half* Ah = (MODE == 0) ? g_Xh : g_Oh;
    const __half* Al = g_Xl;
    const __half* Bh = g_Wh + (size_t)z * NW;

    float c[NT][4];
#pragma unroll
    for (int i = 0; i < NT; i++)
#pragma unroll
        for (int j = 0; j < 4; j++) c[i][j] = 0.0f;

    auto load_stage = [&](int s, int ch) {
        const int k0 = ch * 64;
        const uint32_t se = s * STG;
#pragma unroll
        for (int p = 0; p < 4; p++) {
            int slot = tid + p * 256;
            int r = slot >> 3, cc = (slot & 7) * 8;
            CP16(sbase + (se + r * SROW + cc) * 2,
                 &Ah[(size_t)(m0 + r) * C_DIM + k0 + cc]);
            if (comp)
                CP16(sbase + (se + S_AL + r * SROW + cc) * 2,
                     &Al[(size_t)(m0 + r) * C_DIM + k0 + cc]);
        }
#pragma unroll
        for (int p = 0; p < BP; p++) {
            int slot = tid + p * 256;
            int r = slot >> 3, cc = (slot & 7) * 8;
            CP16(sbase + (se + S_B + r * SROW + cc) * 2,
                 &Bh[(size_t)(n0 + r) * C_DIM + k0 + cc]);
        }
        CP_COMMIT();
    };

    load_stage(0, 0);
    const int NCH = C_DIM / 64;
    for (int ch = 0; ch < NCH; ch++) {
        bool more = (ch + 1 < NCH);
        if (more) load_stage((ch + 1) & 1, ch + 1);
        if (more) CP_WAIT1(); else CP_WAIT0();
        __syncthreads();
        const uint32_t se = (ch & 1) * STG;
#pragma unroll
        for (int ks = 0; ks < 4; ks++) {
            uint32_t ah[4], al[4];
            uint32_t aaddr = sbase + (se +
                (16 * w + (sub & 1) * 8 + rrow) * SROW + 16 * ks + (sub >> 1) * 8) * 2;
            LDSM4(ah, aaddr);
            if (comp) LDSM4(al, aaddr + S_AL * 2);
#pragma unroll
            for (int p = 0; p < NT / 2; p++) {
                uint32_t bh[4];
                uint32_t baddr = sbase + (se + S_B +
                    (16 * p + (sub >> 1) * 8 + rrow) * SROW + 16 * ks + (sub & 1) * 8) * 2;
                LDSM4(bh, baddr);
                mma_f16(c[2 * p], ah, bh);
                mma_f16(c[2 * p + 1], ah, bh + 2);
                if (comp) {
                    mma_f16(c[2 * p], al, bh);
                    mma_f16(c[2 * p + 1], al, bh + 2);
                }
            }
        }
        __syncthreads();
    }

    const int r0 = m0 + 16 * w + g;
    if (MODE == 0) {
#pragma unroll
        for (int nt = 0; nt < NT; nt++) {
            const int head = n0 / 64 + (nt >> 3);       // N-tile covers 2 heads
            const int cb = 8 * (nt & 7) + 2 * t;        // column within head
            size_t o1 = ((size_t)head * T_SEQ + r0) * HEAD_D + cb;
            size_t o2 = ((size_t)head * T_SEQ + r0 + 8) * HEAD_D + cb;
            if (z == 0) {
                uint32_t h0, l0, h1, l1;
                split2(c[nt][0] * QSC, c[nt][1] * QSC, h0, l0);
                split2(c[nt][2] * QSC, c[nt][3] * QSC, h1, l1);
                *(uint32_t*)&g_Qh[o1] = h0; *(uint32_t*)&g_Ql[o1] = l0;
                *(uint32_t*)&g_Qh[o2] = h1; *(uint32_t*)&g_Ql[o2] = l1;
            } else {
                __half* dh = (z == 1) ? g_Kh : g_Vh;
                *(uint32_t*)&dh[o1] = pack_h2(c[nt][0], c[nt][1]);
                *(uint32_t*)&dh[o2] = pack_h2(c[nt][2], c[nt][3]);
            }
        }
    } else {
#pragma unroll
        for (int nt = 0; nt < NT; nt++) {
            int cb = n0 + 8 * nt + 2 * t;
            *(float2*)&outp[(size_t)r0 * C_DIM + cb] = make_float2(c[nt][0], c[nt][1]);
            *(float2*)&outp[(size_t)(r0 + 8) * C_DIM + cb] = make_float2(c[nt][2], c[nt][3]);
        }
    }
}

static constexpr int GEMM0_SMEM = 2 * 27648 * 2;  // 110592 B
static constexpr int GEMM1_SMEM = 2 * 13824 * 2;  // 55296 B

// ----------------------------------------------------------------------------
// Flash attention (causal), log2-domain softmax with fp16x2 ex2.
// CTA = (head, 64 q rows), 4 warps (warp: 16 rows); 64-key tiles (minimal
// register footprint -> 3 CTAs/SM = 12 warps/SM for latency hiding);
// 3-stage cp.async pipeline.
// S: Q hi/lo x K (2 MMA). P: fp16 direct from ex2. PV: 1 MMA. Row sums: ones-MMA.
// Warp-voted rescale skip when no row max changes.
// ----------------------------------------------------------------------------
#define A_VOFF 4608                      // V offset within stage (64*SROW)
#define A_STG 9216                       // stage elems: 2*64*72
static constexpr int ATTN_SMEM = 3 * A_STG * 2;  // 55296 B

__global__ __launch_bounds__(128, 3) void attn_hf()
{
    extern __shared__ __half sa[];
    const uint32_t sbase = smem_u32(sa);
    const int h = blockIdx.y;
    const int qi = gridDim.x - 1 - blockIdx.x;   // long CTAs first
    const int q0 = qi * 64;
    const int tid = threadIdx.x;
    const int w = tid >> 5, lane = tid & 31;
    const int g = lane >> 2, t = lane & 3;
    const int sub = lane >> 3, rrow = lane & 7;

    const __half* Qhp = g_Qh + (size_t)h * T_SEQ * HEAD_D;
    const __half* Qlp = g_Ql + (size_t)h * T_SEQ * HEAD_D;
    const __half* Khp = g_Kh + (size_t)h * T_SEQ * HEAD_D;
    const __half* Vhp = g_Vh + (size_t)h * T_SEQ * HEAD_D;

    const int r0 = q0 + 16 * w + g;

    uint32_t qh[4][4], ql[4][4];
#pragma unroll
    for (int ks = 0; ks < 4; ks++) {
#pragma unroll
        for (int rr = 0; rr < 2; rr++) {
            size_t base = (size_t)(r0 + 8 * rr) * HEAD_D + 16 * ks + 2 * t;
            qh[ks][rr]     = *(const uint32_t*)&Qhp[base];
            qh[ks][rr + 2] = *(const uint32_t*)&Qhp[base + 8];
            ql[ks][rr]     = *(const uint32_t*)&Qlp[base];
            ql[ks][rr + 2] = *(const uint32_t*)&Qlp[base + 8];
        }
    }

    float o[8][4];
#pragma unroll
    for (int i = 0; i < 8; i++)
#pragma unroll
        for (int j = 0; j < 4; j++) o[i][j] = 0.0f;
    float m_[2] = {-1e30f, -1e30f};
    float lsum[4] = {0.0f, 0.0f, 0.0f, 0.0f};
    const uint32_t ones2[2] = {0x3C003C00u, 0x3C003C00u};

    auto load_stage = [&](int j) {
        const int k0 = j * 64;
        const uint32_t se = (j % 3) * A_STG;
#pragma unroll
        for (int p = 0; p < 4; p++) {
            int slot = tid + p * 128;
            int r = slot >> 3, cc = (slot & 7) * 8;
            size_t go = (size_t)(k0 + r) * HEAD_D + cc;
            uint32_t so = (se + r * SROW + cc) * 2;
            CP16(sbase + so, &Khp[go]);
            CP16(sbase + so + A_VOFF * 2, &Vhp[go]);
        }
        CP_COMMIT();
    };

    const int njt = qi + 1;
    load_stage(0);
    if (njt > 1) load_stage(1);
    for (int j = 0; j < njt; j++) {
        if (j + 1 < njt) CP_WAIT1(); else CP_WAIT0();
        __syncthreads();
        if (j + 2 < njt) load_stage(j + 2);

        const int k0 = j * 64;
        const uint32_t se = (j % 3) * A_STG;
        const bool active = (k0 <= q0 + 16 * w + 15);

        if (active) {
            float s[8][4];
#pragma unroll
            for (int i = 0; i < 8; i++)
#pragma unroll
                for (int e = 0; e < 4; e++) s[i][e] = 0.0f;

            // S (log2 domain) = Q' K^T  (Q hi/lo compensated, K rounded)
#pragma unroll
            for (int ks = 0; ks < 4; ks++) {
#pragma unroll
                for (int p = 0; p < 4; p++) {
                    uint32_t kh[4];
                    uint32_t kaddr = sbase + (se +
                        (16 * p + (sub >> 1) * 8 + rrow) * SROW + 16 * ks + (sub & 1) * 8) * 2;
                    LDSM4(kh, kaddr);
                    mma_f16(s[2 * p], qh[ks], kh);
                    mma_f16(s[2 * p], ql[ks], kh);
                    mma_f16(s[2 * p + 1], qh[ks], kh + 2);
                    mma_f16(s[2 * p + 1], ql[ks], kh + 2);
                }
            }

            // causal mask
            if (k0 + 63 > q0 + 16 * w) {
#pragma unroll
                for (int nt = 0; nt < 8; nt++)
#pragma unroll
                    for (int e = 0; e < 4; e++) {
                        int key = k0 + 8 * nt + 2 * t + (e & 1);
                        int row = r0 + 8 * (e >> 1);
                        if (key > row) s[nt][e] = -1e30f;
                    }
            }

            // running max per row (g, g+8)
            float rmax0 = -1e30f, rmax1 = -1e30f;
#pragma unroll
            for (int nt = 0; nt < 8; nt++) {
                rmax0 = fmaxf(rmax0, fmaxf(s[nt][0], s[nt][1]));
                rmax1 = fmaxf(rmax1, fmaxf(s[nt][2], s[nt][3]));
            }
            rmax0 = fmaxf(rmax0, __shfl_xor_sync(0xffffffffu, rmax0, 1));
            rmax0 = fmaxf(rmax0, __shfl_xor_sync(0xffffffffu, rmax0, 2));
            rmax1 = fmaxf(rmax1, __shfl_xor_sync(0xffffffffu, rmax1, 1));
            rmax1 = fmaxf(rmax1, __shfl_xor_sync(0xffffffffu, rmax1, 2));

            float mn0 = fmaxf(m_[0], rmax0), mn1 = fmaxf(m_[1], rmax1);

            // warp-voted skip: if no row's max moved, corr == 1 exactly
            bool chg = (mn0 > m_[0]) || (mn1 > m_[1]);
            if (__any_sync(0xffffffffu, chg)) {
                float corr0 = exp2f(m_[0] - mn0), corr1 = exp2f(m_[1] - mn1);
                lsum[0] *= corr0; lsum[1] *= corr0;
                lsum[2] *= corr1; lsum[3] *= corr1;
#pragma unroll
                for (int nt = 0; nt < 8; nt++) {
                    o[nt][0] *= corr0;
                    o[nt][1] *= corr0;
                    o[nt][2] *= corr1;
                    o[nt][3] *= corr1;
                }
                m_[0] = mn0; m_[1] = mn1;
            }

            // P = 2^(S - m), packed fp16x2 fragments directly
            uint32_t ph[4][4];
#pragma unroll
            for (int ks = 0; ks < 4; ks++) {
                ph[ks][0] = h2exp2(s[2 * ks][0] - m_[0],     s[2 * ks][1] - m_[0]);
                ph[ks][1] = h2exp2(s[2 * ks][2] - m_[1],     s[2 * ks][3] - m_[1]);
                ph[ks][2] = h2exp2(s[2 * ks + 1][0] - m_[0], s[2 * ks + 1][1] - m_[0]);
                ph[ks][3] = h2exp2(s[2 * ks + 1][2] - m_[1], s[2 * ks + 1][3] - m_[1]);
            }

            // row sums via ones-MMA (l accumulates in fp32 on tensor pipe)
#pragma unroll
            for (int ks = 0; ks < 4; ks++) mma_f16(lsum, ph[ks], ones2);

            // O += P V  (V frags via ldmatrix.trans)
#pragma unroll
            for (int ks = 0; ks < 4; ks++) {
#pragma unroll
                for (int p = 0; p < 4; p++) {
                    uint32_t vh[4];
                    uint32_t vaddr = sbase + (se + A_VOFF +
                        (16 * ks + (sub & 1) * 8 + rrow) * SROW + 16 * p + (sub >> 1) * 8) * 2;
                    LDSM4T(vh, vaddr);
                    mma_f16(o[2 * p], ph[ks], vh);
                    mma_f16(o[2 * p + 1], ph[ks], vh + 2);
                }
            }
        }
    }

    // normalize + write O (fp16) in (T, C) layout
    float inv0 = 1.0f / lsum[0], inv1 = 1.0f / lsum[2];
#pragma unroll
    for (int nd = 0; nd < 8; nd++) {
        int col = h * HEAD_D + 8 * nd + 2 * t;
        *(uint32_t*)&g_Oh[(size_t)r0 * C_DIM + col] =
            pack_h2(o[nd][0] * inv0, o[nd][1] * inv0);
        *(uint32_t*)&g_Oh[(size_t)(r0 + 8) * C_DIM + col] =
            pack_h2(o[nd][2] * inv1, o[nd][3] * inv1);
    }
}

// ----------------------------------------------------------------------------
extern "C" void kernel_launch(void* const* d_in, const int* in_sizes, int n_in,
                              void* d_out, int out_size)
{
    const float* x  = (const float*)d_in[0];
    const float* wq = (const float*)d_in[1];
    const float* wk = (const float*)d_in[2];
    const float* wv = (const float*)d_in[3];
    const float* wo = (const float*)d_in[4];
    float* out = (float*)d_out;

    cudaFuncSetAttribute(gemm_hf<0>, cudaFuncAttributeMaxDynamicSharedMemorySize, GEMM0_SMEM);
    cudaFuncSetAttribute(gemm_hf<1>, cudaFuncAttributeMaxDynamicSharedMemorySize, GEMM1_SMEM);
    cudaFuncSetAttribute(attn_hf, cudaFuncAttributeMaxDynamicSharedMemorySize, ATTN_SMEM);

    // 0) one-time conversion
    convert_kernel<<<(NCONV + 255) / 256, 256>>>(x, wq, wk, wv, wo);

    // 1) QKV projections (Q compensated, K/V single-MMA), 128x128 tiles
    gemm_hf<0><<<dim3(C_DIM / 128, T_SEQ / 128, 3), 256, GEMM0_SMEM>>>(nullptr);

    // 2) flash attention: 64-row CTAs, 64-key tiles, 3 CTAs/SM
    attn_hf<<<dim3(T_SEQ / 64, N_HEAD), 128, ATTN_SMEM>>>();

    // 3) output projection -> fp32, 128x64 tiles (wave-fit)
    gemm_hf<1><<<dim3(C_DIM / 64, T_SEQ / 128, 1), 256, GEMM1_SMEM>>>(out);
}